// round 10
// baseline (speedup 1.0000x reference)
#include <cuda_runtime.h>
#include <cuda_bf16.h>
#include <cstdint>

// Problem constants
#define BB    4096
#define DD    128
#define HIST  50
#define TOPN  4
#define PROTO 1024
#define ITEMS 100000
#define KTOT  1152      // 384 text + 768 visual
#define K1    256       // MLP layer1 input
#define D2    64        // MLP layer2 output

typedef unsigned long long ull;

// ---------------- scratch (__device__ globals; no allocation allowed) ----------------
__device__ float2 g_W2T2[(DD/2)*D2];
__device__ float  g_cb[DD];             // bt·Wt_row + bv·Wv_row
__device__ uint4  g_maskh4[BB*PROTO/8]; // bf16 0/1 presence mask (8MB)
__device__ __align__(16) __nv_bfloat16 g_PB2[2*128*1024];  // bf16 split protos^T [split][c][k]
__device__ __align__(16) __nv_bfloat16 g_WB2[2*128*KTOT];  // bf16 split [Wt|Wv]  [split][c][k]
__device__ __align__(16) __nv_bfloat16 g_W1B2[2*128*K1];   // bf16 split W1       [split][c][k]
__device__ __align__(16) __nv_bfloat16 g_XB[2*BB*KTOT];    // bf16 split gathered features
__device__ __align__(16) __nv_bfloat16 g_IFB[2*BB*K1];     // bf16 split inter_feat
__device__ float  g_cinv[BB];           // 1/unique-count
__device__ float  g_z1[BB*DD];
__device__ float  g_z2[BB*D2];
__device__ float  g_s1[DD], g_q1[DD];
__device__ float  g_s2[D2], g_q2[D2];

__device__ __forceinline__ void ffma2(ull &acc, ull a, ull b) {
    asm("fma.rn.f32x2 %0, %1, %2, %0;" : "+l"(acc) : "l"(a), "l"(b));
}
__device__ __forceinline__ float sum2(ull v) {
    return __uint_as_float((unsigned)v) + __uint_as_float((unsigned)(v >> 32));
}
__device__ __forceinline__ void cpa16(void* dst, const void* src) {
    unsigned d = (unsigned)__cvta_generic_to_shared(dst);
    asm volatile("cp.async.cg.shared.global [%0], [%1], 16;" :: "r"(d), "l"(src));
}
__device__ __forceinline__ void cpa_commit() { asm volatile("cp.async.commit_group;"); }
__device__ __forceinline__ void cpa_wait1() { asm volatile("cp.async.wait_group 1;"); }
__device__ __forceinline__ void cpa_wait0() { asm volatile("cp.async.wait_group 0;"); }

// HMMA bf16: D(f32) += A(bf16 m16k16 row) * B(bf16 k16n8 col)
__device__ __forceinline__ void mma_bf16(float* d, uint32_t a0, uint32_t a1,
                                         uint32_t a2, uint32_t a3,
                                         uint32_t b0, uint32_t b1) {
    asm volatile("mma.sync.aligned.m16n8k16.row.col.f32.bf16.bf16.f32 "
                 "{%0,%1,%2,%3},{%4,%5,%6,%7},{%8,%9},{%0,%1,%2,%3};"
                 : "+f"(d[0]), "+f"(d[1]), "+f"(d[2]), "+f"(d[3])
                 : "r"(a0), "r"(a1), "r"(a2), "r"(a3), "r"(b0), "r"(b1));
}
__device__ __forceinline__ uint32_t pk_bf2(float lo, float hi) {
    uint32_t r;
    asm("cvt.rn.bf16x2.f32 %0, %1, %2;" : "=r"(r) : "f"(hi), "f"(lo));
    return r;
}
__device__ __forceinline__ void split2(float v0, float v1, uint32_t &hi, uint32_t &lo) {
    __nv_bfloat16 h0 = __float2bfloat16(v0), h1 = __float2bfloat16(v1);
    uint16_t u0, u1; memcpy(&u0, &h0, 2); memcpy(&u1, &h1, 2);
    hi = (uint32_t)u0 | ((uint32_t)u1 << 16);
    lo = pk_bf2(v0 - __bfloat162float(h0), v1 - __bfloat162float(h1));
}

// ---------------- prep: weight splits/layouts + zero stats + cb ---------------------
__global__ void k_prep(const float* __restrict__ Wt, const float* __restrict__ Wv,
                       const float* __restrict__ W1, const float* __restrict__ W2,
                       const float* __restrict__ protos,
                       const float* __restrict__ bt, const float* __restrict__ bv) {
    int tid = threadIdx.x;
    if (blockIdx.x >= 296) {   // cb part: 16 blocks x 8 warps = 128 columns
        int c = (blockIdx.x - 296)*8 + (tid >> 5);
        int l = tid & 31;
        float s = 0.f;
        for (int k = l; k < 384; k += 32) s += bt[k] * Wt[c*384 + k];
        for (int k = l; k < 768; k += 32) s += bv[k] * Wv[c*768 + k];
        #pragma unroll
        for (int o = 16; o; o >>= 1) s += __shfl_down_sync(0xffffffffu, s, o);
        if (l == 0) g_cb[c] = s;
        return;
    }
    const int n_wb = 128*KTOT;
    const int n_pb = 128*1024;
    const int n_w1 = 128*K1;
    const int n_w2 = (DD/2)*D2;
    const int n_z  = 2*DD + 2*D2;
    int total = n_wb + n_pb + n_w1 + n_w2 + n_z;
    for (int i = blockIdx.x*blockDim.x + tid; i < total; i += 296*blockDim.x) {
        if (i < n_wb) {
            int c = i / KTOT, k = i % KTOT;
            float v = (k < 384) ? Wt[c*384 + k] : Wv[c*768 + (k - 384)];
            __nv_bfloat16 b1 = __float2bfloat16(v);
            g_WB2[i]            = b1;
            g_WB2[128*KTOT + i] = __float2bfloat16(v - __bfloat162float(b1));
        } else if (i < n_wb + n_pb) {
            int j = i - n_wb; int c = j & 127; int k = j >> 7;
            float p = protos[k*DD + c];
            __nv_bfloat16 b1 = __float2bfloat16(p);
            g_PB2[c*1024 + k]          = b1;
            g_PB2[131072 + c*1024 + k] = __float2bfloat16(p - __bfloat162float(b1));
        } else if (i < n_wb + n_pb + n_w1) {
            int j = i - n_wb - n_pb;
            float v = W1[j];
            __nv_bfloat16 b1 = __float2bfloat16(v);
            g_W1B2[j]          = b1;
            g_W1B2[128*K1 + j] = __float2bfloat16(v - __bfloat162float(b1));
        } else if (i < n_wb + n_pb + n_w1 + n_w2) {
            int j = i - n_wb - n_pb - n_w1; int k2 = j / D2, c = j % D2;
            g_W2T2[j] = make_float2(W2[c*DD + 2*k2], W2[c*DD + 2*k2 + 1]);
        } else {
            int j = i - n_wb - n_pb - n_w1 - n_w2;
            if (j < DD)            g_s1[j] = 0.f;
            else if (j < 2*DD)     g_q1[j-DD] = 0.f;
            else if (j < 2*DD+D2)  g_s2[j-2*DD] = 0.f;
            else                   g_q2[j-2*DD-D2] = 0.f;
        }
    }
}

// ---------------- fused: feature gather/split + mask build + prompt gathers ---------
__global__ void __launch_bounds__(288) k_xbm(
        const int* __restrict__ nodes_u, const int* __restrict__ nodes_v,
        const int* __restrict__ nodes_d, const int* __restrict__ inter_items,
        const int* __restrict__ top_n,
        const float* __restrict__ pre_text, const float* __restrict__ pre_visual,
        const float* __restrict__ up, const float* __restrict__ dp,
        float* __restrict__ out_pu, float* __restrict__ out_pd) {
    __shared__ unsigned bm[PROTO/32];
    int s = blockIdx.x, tid = threadIdx.x;
    // feature gather (independent of mask)
    int row = nodes_v[s];
    float4 v = (tid < 96) ? ((const float4*)(pre_text + (size_t)row*384))[tid]
                          : ((const float4*)(pre_visual + (size_t)row*768))[tid - 96];
    if (tid < 32) bm[tid] = 0u;
    __syncthreads();
    if (tid < HIST) {
        int item = inter_items[s*HIST + tid];
        int4 r1 = ((const int4*)top_n)[item];
        int4 r2 = ((const int4*)top_n)[item + ITEMS];
        atomicOr(&bm[r1.x >> 5], 1u << (r1.x & 31));
        atomicOr(&bm[r1.y >> 5], 1u << (r1.y & 31));
        atomicOr(&bm[r1.z >> 5], 1u << (r1.z & 31));
        atomicOr(&bm[r1.w >> 5], 1u << (r1.w & 31));
        atomicOr(&bm[r2.x >> 5], 1u << (r2.x & 31));
        atomicOr(&bm[r2.y >> 5], 1u << (r2.y & 31));
        atomicOr(&bm[r2.z >> 5], 1u << (r2.z & 31));
        atomicOr(&bm[r2.w >> 5], 1u << (r2.w & 31));
    }
    // write feature split while atomics land
    {
        uint32_t h0, l0, h1, l1;
        split2(v.x, v.y, h0, l0);
        split2(v.z, v.w, h1, l1);
        size_t off = (size_t)s*KTOT + 4*tid;
        *(uint2*)(g_XB + off)                   = make_uint2(h0, h1);
        *(uint2*)(g_XB + (size_t)BB*KTOT + off) = make_uint2(l0, l1);
    }
    __syncthreads();
    if (tid < 32) {
        unsigned c = __popc(bm[tid]);
        #pragma unroll
        for (int o = 16; o; o >>= 1) c += __shfl_down_sync(0xffffffffu, c, o);
        if (tid == 0) g_cinv[s] = 1.0f / (float)c;
    }
    if (tid < 128) {
        unsigned w = bm[tid >> 2];
        int sh = (tid & 3) * 8;
        uint32_t pk[4];
        #pragma unroll
        for (int q = 0; q < 4; ++q) {
            uint32_t lo = ((w >> (sh + 2*q)) & 1) ? 0x3F80u : 0u;
            uint32_t hi = ((w >> (sh + 2*q + 1)) & 1) ? 0x3F80u : 0u;
            pk[q] = lo | (hi << 16);
        }
        g_maskh4[(size_t)s*128 + tid] = make_uint4(pk[0], pk[1], pk[2], pk[3]);
        out_pu[s*DD + tid] = up[nodes_u[s]*DD + tid];
        out_pd[s*DD + tid] = dp[nodes_d[s]*DD + tid];
    }
}

// ===================================================================================
// HMMA GEMM skeleton (M=64): 256 thr; per CTA M=64 samples, N=128 cols, BK=64.
// smem row stride 72 bf16 (144B). Warp w covers cols [w*16, w*16+16).
// ===================================================================================
#define EH_BK   64
#define EH_ST   72
#define EH_ABUF (64*EH_ST*2)        // 9216
#define EH_BBUF (128*EH_ST*2)       // 18432
#define EH_BUF  (EH_ABUF + EH_BBUF) // 27648
#define EH_SMEM (3*EH_BUF)          // 82944

#define MMA_FRAG_LOOP(A_, B_)                                                   \
    _Pragma("unroll")                                                           \
    for (int ks = 0; ks < EH_BK/16; ++ks) {                                     \
        int k = ks*16 + kb;                                                     \
        _Pragma("unroll")                                                       \
        for (int mi = 0; mi < 4; ++mi) {                                        \
            int r0 = mi*16 + gr;                                                \
            uint32_t a0 = *(const uint32_t*)&A_[r0*EH_ST + k];                  \
            uint32_t a1 = *(const uint32_t*)&A_[(r0+8)*EH_ST + k];              \
            uint32_t a2 = *(const uint32_t*)&A_[r0*EH_ST + k + 8];              \
            uint32_t a3 = *(const uint32_t*)&A_[(r0+8)*EH_ST + k + 8];          \
            _Pragma("unroll")                                                   \
            for (int ni = 0; ni < 2; ++ni) {                                    \
                int n = w*16 + ni*8 + gr;                                       \
                uint32_t b0 = *(const uint32_t*)&B_[n*EH_ST + k];               \
                uint32_t b1 = *(const uint32_t*)&B_[n*EH_ST + k + 8];           \
                mma_bf16(d[mi][ni], a0, a1, a2, a3, b0, b1);                    \
            }                                                                   \
        }                                                                       \
    }

#define MMA_PIPE(NCH_)                                                          \
    stage(0, 0); stage(1, 1);                                                   \
    _Pragma("unroll 1")                                                         \
    for (int ch = 0; ch < (NCH_); ++ch) {                                       \
        __syncthreads();                                                        \
        if (ch + 2 < (NCH_)) stage(ch + 2, (ch + 2) % 3);                       \
        if (ch + 2 < (NCH_)) { asm volatile("cp.async.wait_group 2;"); }        \
        else if (ch + 1 < (NCH_)) cpa_wait1();                                  \
        else cpa_wait0();                                                       \
        __syncthreads();                                                        \
        const __nv_bfloat16* A = (const __nv_bfloat16*)(sm + (ch % 3)*EH_BUF);  \
        const __nv_bfloat16* B = (const __nv_bfloat16*)(sm + (ch % 3)*EH_BUF + EH_ABUF); \
        MMA_FRAG_LOOP(A, B);                                                    \
    }

#define MMA_DECL                                                                \
    int tid = threadIdx.x;                                                      \
    int w = tid >> 5, lane = tid & 31;                                          \
    int gr = lane >> 2, kb = (lane & 3) * 2;                                    \
    float d[4][2][4];                                                           \
    _Pragma("unroll")                                                           \
    for (int mi = 0; mi < 4; ++mi)                                              \
        _Pragma("unroll")                                                       \
        for (int ni = 0; ni < 2; ++ni)                                          \
            _Pragma("unroll")                                                   \
            for (int q = 0; q < 4; ++q) d[mi][ni][q] = 0.f;

// stage A (64 rows x 128B) + B (128 rows x 128B) with given gmem row strides
#define STAGE_AB(Ad_, Bd_, abase_, astride_, bbase_, bstride_)                  \
    _Pragma("unroll")                                                           \
    for (int j = 0; j < 2; ++j) {                                               \
        int idx = tid + j*256; int r = idx >> 3, pc = idx & 7;                  \
        cpa16((Ad_) + r*144 + pc*16, (abase_) + (size_t)r*(astride_) + pc*16);  \
    }                                                                           \
    _Pragma("unroll")                                                           \
    for (int i = 0; i < 4; ++i) {                                               \
        int idx = tid + i*256; int c = idx >> 3, pc = idx & 7;                  \
        cpa16((Bd_) + c*144 + pc*16, (bbase_) + (size_t)c*(bstride_) + pc*16);  \
    }                                                                           \
    cpa_commit();

// ---------------- h_u body: D = mask @ (P1 | P2 stacked in K) -----------------------
__device__ __forceinline__ void hu_body(char* sm, int blk,
                                        const int* __restrict__ nodes_d,
                                        const float* __restrict__ dp,
                                        float* __restrict__ out_hu) {
    MMA_DECL;
    auto stage = [&](int ch, int b) {
        char* Ad = sm + b*EH_BUF;
        char* Bd = Ad + EH_ABUF;
        int k0 = ch * EH_BK;
        int split = k0 >> 10, kk = k0 & 1023;
        const char* abase = (const char*)g_maskh4 + (size_t)blk*64*2048 + kk*2;
        const char* bbase = (const char*)g_PB2 + ((size_t)split << 18) + kk*2;
        STAGE_AB(Ad, Bd, abase, 2048, bbase, 2048);
    };
    MMA_PIPE(32);
    #pragma unroll
    for (int mi = 0; mi < 4; ++mi) {
        #pragma unroll
        for (int rr = 0; rr < 2; ++rr) {
            int s = blk*64 + mi*16 + gr + rr*8;
            float inv = g_cinv[s];
            const float* pdr = dp + nodes_d[s]*DD;
            #pragma unroll
            for (int ni = 0; ni < 2; ++ni) {
                int c = w*16 + ni*8 + (lane & 3)*2;
                float h0 = d[mi][ni][rr*2]   * inv;
                float h1 = d[mi][ni][rr*2+1] * inv;
                *(float2*)&out_hu[s*DD + c] = make_float2(h0, h1);
                float2 pd = *(const float2*)&pdr[c];
                uint32_t hi, lo;
                split2(h0 + pd.x, h1 + pd.y, hi, lo);
                *(uint32_t*)&g_IFB[(size_t)s*K1 + c]        = hi;
                *(uint32_t*)&g_IFB[(size_t)(BB + s)*K1 + c] = lo;
            }
        }
    }
}

// ---------------- e body: x1w1 + x1w2 + x2w1 (K_ext = 3*1152) -----------------------
__device__ __forceinline__ void e_body(char* sm, int blk,
                                       const int* __restrict__ nodes_v,
                                       const float* __restrict__ ip) {
    MMA_DECL;
    auto stage = [&](int ch, int b) {
        char* Ad = sm + b*EH_BUF;
        char* Bd = Ad + EH_ABUF;
        int seg = ch / 18;
        int kk = (ch % 18) * EH_BK;
        int sa = (seg == 2) ? 1 : 0;
        int sb = (seg == 1) ? 1 : 0;
        const char* abase = (const char*)g_XB + (size_t)sa*BB*KTOT*2
                          + (size_t)blk*64*(KTOT*2) + kk*2;
        const char* bbase = (const char*)g_WB2 + (size_t)sb*128*KTOT*2 + kk*2;
        STAGE_AB(Ad, Bd, abase, KTOT*2, bbase, KTOT*2);
    };
    MMA_PIPE(54);
    #pragma unroll
    for (int mi = 0; mi < 4; ++mi) {
        #pragma unroll
        for (int rr = 0; rr < 2; ++rr) {
            int s = blk*64 + mi*16 + gr + rr*8;
            int iv = nodes_v[s];
            #pragma unroll
            for (int ni = 0; ni < 2; ++ni) {
                int c = w*16 + ni*8 + (lane & 3)*2;
                float2 cbv = *(const float2*)&g_cb[c];
                float2 ipv = *(const float2*)&ip[(size_t)iv*DD + c];
                float e0 = d[mi][ni][rr*2]   - cbv.x + ipv.x;
                float e1 = d[mi][ni][rr*2+1] - cbv.y + ipv.y;
                uint32_t hi, lo;
                split2(e0, e1, hi, lo);
                *(uint32_t*)&g_IFB[(size_t)s*K1 + DD + c]        = hi;
                *(uint32_t*)&g_IFB[(size_t)(BB + s)*K1 + DD + c] = lo;
            }
        }
    }
}

// fused: blocks [0,64) do e, [64,128) do hu
__global__ void __launch_bounds__(256) k_eh(const int* __restrict__ nodes_v,
                                            const float* __restrict__ ip,
                                            const int* __restrict__ nodes_d,
                                            const float* __restrict__ dp,
                                            float* __restrict__ out_hu) {
    extern __shared__ char sm[];
    if (blockIdx.x < 64) e_body(sm, blockIdx.x, nodes_v, ip);
    else                 hu_body(sm, blockIdx.x - 64, nodes_d, dp, out_hu);
}

// ---------------- z1 via mma.sync: relu(IF @ W1^T + b1) + BN stats ------------------
__global__ void __launch_bounds__(256) k_z1m(const float* __restrict__ b1) {
    extern __shared__ char sm[];
    int blk = blockIdx.x;
    MMA_DECL;
    auto stage = [&](int ch, int b) {
        char* Ad = sm + b*EH_BUF;
        char* Bd = Ad + EH_ABUF;
        int seg = ch / 4;                  // 12 chunks: 3 segments x 4
        int kk = (ch % 4) * EH_BK;
        int sa = (seg == 2) ? 1 : 0;
        int sb = (seg == 1) ? 1 : 0;
        const char* abase = (const char*)g_IFB + (size_t)sa*BB*K1*2
                          + (size_t)blk*64*(K1*2) + kk*2;
        const char* bbase = (const char*)g_W1B2 + (size_t)sb*128*K1*2 + kk*2;
        STAGE_AB(Ad, Bd, abase, K1*2, bbase, K1*2);
    };
    MMA_PIPE(12);
    float2 bb[2];
    bb[0] = *(const float2*)&b1[w*16 + (lane & 3)*2];
    bb[1] = *(const float2*)&b1[w*16 + 8 + (lane & 3)*2];
    float ps[2][2] = {{0,0},{0,0}}, pq[2][2] = {{0,0},{0,0}};
    #pragma unroll
    for (int mi = 0; mi < 4; ++mi) {
        #pragma unroll
        for (int rr = 0; rr < 2; ++rr) {
            int s = blk*64 + mi*16 + gr + rr*8;
            #pragma unroll
            for (int ni = 0; ni < 2; ++ni) {
                int c = w*16 + ni*8 + (lane & 3)*2;
                float z0 = d[mi][ni][rr*2]   + bb[ni].x; z0 = z0 > 0.f ? z0 : 0.f;
                float z1v = d[mi][ni][rr*2+1] + bb[ni].y; z1v = z1v > 0.f ? z1v : 0.f;
                *(float2*)&g_z1[s*DD + c] = make_float2(z0, z1v);
                ps[ni][0] += z0; ps[ni][1] += z1v;
                pq[ni][0] += z0*z0; pq[ni][1] += z1v*z1v;
            }
        }
    }
    #pragma unroll
    for (int ni = 0; ni < 2; ++ni) {
        #pragma unroll
        for (int q = 0; q < 2; ++q) {
            #pragma unroll
            for (int o = 4; o <= 16; o <<= 1) {
                ps[ni][q] += __shfl_xor_sync(0xffffffffu, ps[ni][q], o);
                pq[ni][q] += __shfl_xor_sync(0xffffffffu, pq[ni][q], o);
            }
        }
        if (lane < 4) {
            int c = w*16 + ni*8 + lane*2;
            atomicAdd(&g_s1[c],   ps[ni][0]); atomicAdd(&g_s1[c+1], ps[ni][1]);
            atomicAdd(&g_q1[c],   pq[ni][0]); atomicAdd(&g_q1[c+1], pq[ni][1]);
        }
    }
}

// ---------------- z2 = relu(BN(z1) @ W2^T + b2) + partial BN stats ------------------
// 64 blocks x 256 thr, 64 samples/block; BN-affine fold computed inline (no k_m1).
#define Z2_SMEM (32768 + 32768)
__global__ void __launch_bounds__(256) k_z2(const float* __restrict__ b2,
                                            const float* __restrict__ g1,
                                            const float* __restrict__ be1) {
    extern __shared__ char zs[];
    float2* W2s = (float2*)zs;                 // 32KB
    float*  X   = (float*)(zs + 32768);        // 64 x 128 = 32KB
    __shared__ float A1[DD], D1[DD];
    int blk = blockIdx.x, tid = threadIdx.x;
    int c = tid & 63, h = tid >> 6;            // col, sample-quarter
    {
        const float4* src = (const float4*)g_W2T2;
        float4* dst = (float4*)W2s;
        #pragma unroll
        for (int i = 0; i < 8; ++i)
            cpa16(dst + tid + i*256, src + tid + i*256);
        cpa_commit();
    }
    if (tid < DD) {
        float m = g_s1[tid] * (1.0f/BB);
        float v = g_q1[tid] * (1.0f/BB) - m*m;
        float r = rsqrtf(v + 1e-5f);
        float a = g1[tid] * r;
        A1[tid] = a;
        D1[tid] = be1[tid] - m*a;
    }
    __syncthreads();
    for (int l = tid; l < 64*DD; l += 256) {
        int s = l >> 7, kk = l & 127;
        X[l] = g_z1[(blk*64 + s)*DD + kk] * A1[kk] + D1[kk];
    }
    cpa_wait0();
    __syncthreads();
    ull acc[16];
    #pragma unroll
    for (int i = 0; i < 16; ++i) acc[i] = 0ull;
    #pragma unroll 4
    for (int p = 0; p < DD/2; ++p) {
        ull wv = *(const ull*)&W2s[p*D2 + c];
        #pragma unroll
        for (int i = 0; i < 16; ++i) {
            ull x = *(const ull*)&X[(h*16 + i)*DD + 2*p];
            ffma2(acc[i], wv, x);
        }
    }
    float bb = b2[c];
    float lsum = 0.f, lss = 0.f;
    #pragma unroll
    for (int i = 0; i < 16; ++i) {
        float z = sum2(acc[i]) + bb;
        z = z > 0.f ? z : 0.f;
        g_z2[(blk*64 + h*16 + i)*D2 + c] = z;
        lsum += z; lss += z*z;
    }
    atomicAdd(&g_s2[c], lsum);
    atomicAdd(&g_q2[c], lss);
}

// ---------------- pred = sigmoid(BN(z2) @ Wp^T + bp), BN fold inline ---------------
__global__ void k_pred(const float* __restrict__ Wp, const float* __restrict__ bp,
                       const float* __restrict__ g2, const float* __restrict__ be2,
                       float* __restrict__ out_pred) {
    __shared__ float A2[D2], D2v[D2];
    int tid = threadIdx.x;
    if (tid < D2) {
        float m = g_s2[tid] * (1.0f/BB);
        float v = g_q2[tid] * (1.0f/BB) - m*m;
        float r = rsqrtf(v + 1e-5f);
        float a = g2[tid] * r;
        A2[tid] = a;
        D2v[tid] = be2[tid] - m*a;
    }
    __syncthreads();
    int warp = (blockIdx.x*blockDim.x + tid) >> 5;
    int lane = tid & 31;
    if (warp >= BB) return;
    float t = 0.f;
    #pragma unroll
    for (int j = 0; j < 2; ++j) {
        int cidx = lane + j*32;
        float f2 = g_z2[warp*D2 + cidx] * A2[cidx] + D2v[cidx];
        t += f2 * Wp[cidx];
    }
    #pragma unroll
    for (int o = 16; o; o >>= 1) t += __shfl_down_sync(0xffffffffu, t, o);
    if (lane == 0) out_pred[warp] = 1.0f / (1.0f + expf(-(t + bp[0])));
}

// ---------------- launch ------------------------------------------------------------
extern "C" void kernel_launch(void* const* d_in, const int* in_sizes, int n_in,
                              void* d_out, int out_size) {
    const int*   nodes_u     = (const int*)  d_in[0];
    const int*   nodes_v     = (const int*)  d_in[1];
    const int*   nodes_d     = (const int*)  d_in[2];
    const int*   inter_items = (const int*)  d_in[3];
    const int*   top_n       = (const int*)  d_in[4];
    const float* protos      = (const float*)d_in[5];
    const float* pre_text    = (const float*)d_in[6];
    const float* pre_visual  = (const float*)d_in[7];
    const float* Wt          = (const float*)d_in[8];
    const float* bt          = (const float*)d_in[9];
    const float* Wv          = (const float*)d_in[10];
    const float* bv          = (const float*)d_in[11];
    const float* up          = (const float*)d_in[12];
    const float* ip          = (const float*)d_in[13];
    const float* dp          = (const float*)d_in[14];
    const float* W1          = (const float*)d_in[15];
    const float* b1          = (const float*)d_in[16];
    const float* g1          = (const float*)d_in[17];
    const float* be1         = (const float*)d_in[18];
    const float* W2          = (const float*)d_in[19];
    const float* b2          = (const float*)d_in[20];
    const float* g2          = (const float*)d_in[21];
    const float* be2         = (const float*)d_in[22];
    const float* Wp          = (const float*)d_in[23];
    const float* bp          = (const float*)d_in[24];

    float* out      = (float*)d_out;
    float* out_pred = out;
    float* out_pu   = out + BB;
    float* out_hu   = out + BB + BB*DD;
    float* out_pd   = out + BB + 2*BB*DD;

    cudaFuncSetAttribute(k_eh,  cudaFuncAttributeMaxDynamicSharedMemorySize, EH_SMEM);
    cudaFuncSetAttribute(k_z1m, cudaFuncAttributeMaxDynamicSharedMemorySize, EH_SMEM);
    cudaFuncSetAttribute(k_z2,  cudaFuncAttributeMaxDynamicSharedMemorySize, Z2_SMEM);

    k_prep<<<312, 256>>>(Wt, Wv, W1, W2, protos, bt, bv);
    k_xbm<<<BB, 288>>>(nodes_u, nodes_v, nodes_d, inter_items, top_n,
                       pre_text, pre_visual, up, dp, out_pu, out_pd);
    k_eh<<<128, 256, EH_SMEM>>>(nodes_v, ip, nodes_d, dp, out_hu);
    k_z1m<<<BB/64, 256, EH_SMEM>>>(b1);
    k_z2<<<BB/64, 256, Z2_SMEM>>>(b2, g1, be1);
    k_pred<<<BB/8, 256>>>(Wp, bp, g2, be2, out_pred);
}

// round 11
// speedup vs baseline: 1.0885x; 1.0885x over previous
#include <cuda_runtime.h>
#include <cuda_bf16.h>
#include <cstdint>

// Problem constants
#define BB    4096
#define DD    128
#define HIST  50
#define TOPN  4
#define PROTO 1024
#define ITEMS 100000
#define KTOT  1152      // 384 text + 768 visual
#define K1    256       // MLP layer1 input
#define D2    64        // MLP layer2 output
#define ESG   16        // samples per z2 block

typedef unsigned long long ull;

// ---------------- scratch (__device__ globals; no allocation allowed) ----------------
__device__ float2 g_W2T2[(DD/2)*D2];
__device__ float  g_cb[DD];             // bt·Wt_row + bv·Wv_row
__device__ uint4  g_maskh4[BB*PROTO/8]; // bf16 0/1 presence mask (8MB)
__device__ __align__(16) __nv_bfloat16 g_PB2[2*128*1024];  // bf16 split protos^T [split][c][k]
__device__ __align__(16) __nv_bfloat16 g_WB2[2*128*KTOT];  // bf16 split [Wt|Wv]  [split][c][k]
__device__ __align__(16) __nv_bfloat16 g_W1B2[2*128*K1];   // bf16 split W1       [split][c][k]
__device__ __align__(16) __nv_bfloat16 g_XB[2*BB*KTOT];    // bf16 split gathered features
__device__ __align__(16) __nv_bfloat16 g_IFB[2*BB*K1];     // bf16 split inter_feat
__device__ float  g_cinv[BB];           // 1/unique-count
__device__ float  g_z1[BB*DD];
__device__ float  g_z2[BB*D2];
__device__ float  g_s1[DD], g_q1[DD];
__device__ float  g_s2[D2], g_q2[D2];

__device__ __forceinline__ void ffma2(ull &acc, ull a, ull b) {
    asm("fma.rn.f32x2 %0, %1, %2, %0;" : "+l"(acc) : "l"(a), "l"(b));
}
__device__ __forceinline__ float sum2(ull v) {
    return __uint_as_float((unsigned)v) + __uint_as_float((unsigned)(v >> 32));
}
__device__ __forceinline__ void cpa16(void* dst, const void* src) {
    unsigned d = (unsigned)__cvta_generic_to_shared(dst);
    asm volatile("cp.async.cg.shared.global [%0], [%1], 16;" :: "r"(d), "l"(src));
}
__device__ __forceinline__ void cpa_commit() { asm volatile("cp.async.commit_group;"); }
__device__ __forceinline__ void cpa_wait1() { asm volatile("cp.async.wait_group 1;"); }
__device__ __forceinline__ void cpa_wait0() { asm volatile("cp.async.wait_group 0;"); }

// HMMA bf16: D(f32) += A(bf16 m16k16 row) * B(bf16 k16n8 col)
__device__ __forceinline__ void mma_bf16(float* d, uint32_t a0, uint32_t a1,
                                         uint32_t a2, uint32_t a3,
                                         uint32_t b0, uint32_t b1) {
    asm volatile("mma.sync.aligned.m16n8k16.row.col.f32.bf16.bf16.f32 "
                 "{%0,%1,%2,%3},{%4,%5,%6,%7},{%8,%9},{%0,%1,%2,%3};"
                 : "+f"(d[0]), "+f"(d[1]), "+f"(d[2]), "+f"(d[3])
                 : "r"(a0), "r"(a1), "r"(a2), "r"(a3), "r"(b0), "r"(b1));
}
__device__ __forceinline__ uint32_t pk_bf2(float lo, float hi) {
    uint32_t r;
    asm("cvt.rn.bf16x2.f32 %0, %1, %2;" : "=r"(r) : "f"(hi), "f"(lo));
    return r;
}
__device__ __forceinline__ void split2(float v0, float v1, uint32_t &hi, uint32_t &lo) {
    __nv_bfloat16 h0 = __float2bfloat16(v0), h1 = __float2bfloat16(v1);
    uint16_t u0, u1; memcpy(&u0, &h0, 2); memcpy(&u1, &h1, 2);
    hi = (uint32_t)u0 | ((uint32_t)u1 << 16);
    lo = pk_bf2(v0 - __bfloat162float(h0), v1 - __bfloat162float(h1));
}

// ---------------- prep: weight splits/layouts + zero stats + cb ---------------------
__global__ void k_prep(const float* __restrict__ Wt, const float* __restrict__ Wv,
                       const float* __restrict__ W1, const float* __restrict__ W2,
                       const float* __restrict__ protos,
                       const float* __restrict__ bt, const float* __restrict__ bv) {
    int tid = threadIdx.x;
    if (blockIdx.x >= 296) {   // cb part: 16 blocks x 8 warps = 128 columns
        int c = (blockIdx.x - 296)*8 + (tid >> 5);
        int l = tid & 31;
        float s = 0.f;
        for (int k = l; k < 384; k += 32) s += bt[k] * Wt[c*384 + k];
        for (int k = l; k < 768; k += 32) s += bv[k] * Wv[c*768 + k];
        #pragma unroll
        for (int o = 16; o; o >>= 1) s += __shfl_down_sync(0xffffffffu, s, o);
        if (l == 0) g_cb[c] = s;
        return;
    }
    const int n_wb = 128*KTOT;
    const int n_pb = 128*1024;
    const int n_w1 = 128*K1;
    const int n_w2 = (DD/2)*D2;
    const int n_z  = 2*DD + 2*D2;
    int total = n_wb + n_pb + n_w1 + n_w2 + n_z;
    for (int i = blockIdx.x*blockDim.x + tid; i < total; i += 296*blockDim.x) {
        if (i < n_wb) {
            int c = i / KTOT, k = i % KTOT;
            float v = (k < 384) ? Wt[c*384 + k] : Wv[c*768 + (k - 384)];
            __nv_bfloat16 b1 = __float2bfloat16(v);
            g_WB2[i]            = b1;
            g_WB2[128*KTOT + i] = __float2bfloat16(v - __bfloat162float(b1));
        } else if (i < n_wb + n_pb) {
            int j = i - n_wb; int c = j & 127; int k = j >> 7;
            float p = protos[k*DD + c];
            __nv_bfloat16 b1 = __float2bfloat16(p);
            g_PB2[c*1024 + k]          = b1;
            g_PB2[131072 + c*1024 + k] = __float2bfloat16(p - __bfloat162float(b1));
        } else if (i < n_wb + n_pb + n_w1) {
            int j = i - n_wb - n_pb;
            float v = W1[j];
            __nv_bfloat16 b1 = __float2bfloat16(v);
            g_W1B2[j]          = b1;
            g_W1B2[128*K1 + j] = __float2bfloat16(v - __bfloat162float(b1));
        } else if (i < n_wb + n_pb + n_w1 + n_w2) {
            int j = i - n_wb - n_pb - n_w1; int k2 = j / D2, c = j % D2;
            g_W2T2[j] = make_float2(W2[c*DD + 2*k2], W2[c*DD + 2*k2 + 1]);
        } else {
            int j = i - n_wb - n_pb - n_w1 - n_w2;
            if (j < DD)            g_s1[j] = 0.f;
            else if (j < 2*DD)     g_q1[j-DD] = 0.f;
            else if (j < 2*DD+D2)  g_s2[j-2*DD] = 0.f;
            else                   g_q2[j-2*DD-D2] = 0.f;
        }
    }
}

// ---------------- fused: feature gather/split + mask build + prompt gathers ---------
__global__ void __launch_bounds__(288) k_xbm(
        const int* __restrict__ nodes_u, const int* __restrict__ nodes_v,
        const int* __restrict__ nodes_d, const int* __restrict__ inter_items,
        const int* __restrict__ top_n,
        const float* __restrict__ pre_text, const float* __restrict__ pre_visual,
        const float* __restrict__ up, const float* __restrict__ dp,
        float* __restrict__ out_pu, float* __restrict__ out_pd) {
    __shared__ unsigned bm[PROTO/32];
    int s = blockIdx.x, tid = threadIdx.x;
    int row = nodes_v[s];
    float4 v = (tid < 96) ? ((const float4*)(pre_text + (size_t)row*384))[tid]
                          : ((const float4*)(pre_visual + (size_t)row*768))[tid - 96];
    if (tid < 32) bm[tid] = 0u;
    __syncthreads();
    if (tid < HIST) {
        int item = inter_items[s*HIST + tid];
        int4 r1 = ((const int4*)top_n)[item];
        int4 r2 = ((const int4*)top_n)[item + ITEMS];
        atomicOr(&bm[r1.x >> 5], 1u << (r1.x & 31));
        atomicOr(&bm[r1.y >> 5], 1u << (r1.y & 31));
        atomicOr(&bm[r1.z >> 5], 1u << (r1.z & 31));
        atomicOr(&bm[r1.w >> 5], 1u << (r1.w & 31));
        atomicOr(&bm[r2.x >> 5], 1u << (r2.x & 31));
        atomicOr(&bm[r2.y >> 5], 1u << (r2.y & 31));
        atomicOr(&bm[r2.z >> 5], 1u << (r2.z & 31));
        atomicOr(&bm[r2.w >> 5], 1u << (r2.w & 31));
    }
    {
        uint32_t h0, l0, h1, l1;
        split2(v.x, v.y, h0, l0);
        split2(v.z, v.w, h1, l1);
        size_t off = (size_t)s*KTOT + 4*tid;
        *(uint2*)(g_XB + off)                   = make_uint2(h0, h1);
        *(uint2*)(g_XB + (size_t)BB*KTOT + off) = make_uint2(l0, l1);
    }
    __syncthreads();
    if (tid < 32) {
        unsigned c = __popc(bm[tid]);
        #pragma unroll
        for (int o = 16; o; o >>= 1) c += __shfl_down_sync(0xffffffffu, c, o);
        if (tid == 0) g_cinv[s] = 1.0f / (float)c;
    }
    if (tid < 128) {
        unsigned w = bm[tid >> 2];
        int sh = (tid & 3) * 8;
        uint32_t pk[4];
        #pragma unroll
        for (int q = 0; q < 4; ++q) {
            uint32_t lo = ((w >> (sh + 2*q)) & 1) ? 0x3F80u : 0u;
            uint32_t hi = ((w >> (sh + 2*q + 1)) & 1) ? 0x3F80u : 0u;
            pk[q] = lo | (hi << 16);
        }
        g_maskh4[(size_t)s*128 + tid] = make_uint4(pk[0], pk[1], pk[2], pk[3]);
        out_pu[s*DD + tid] = up[nodes_u[s]*DD + tid];
        out_pd[s*DD + tid] = dp[nodes_d[s]*DD + tid];
    }
}

// ===================================================================================
// HMMA GEMM skeleton (M=32): 256 thr; per CTA M=32 samples, N=128 cols, BK=64.
// smem row stride 72 bf16 (144B). Warp w covers cols [w*16, w*16+16).
// ===================================================================================
#define HU_BK   64
#define HU_ST   72
#define HU_ABUF (32*HU_ST*2)
#define HU_BBUF (128*HU_ST*2)
#define HU_BUF  (HU_ABUF + HU_BBUF)
#define HU_SMEM (3*HU_BUF)          // 69120 B

#define MMA_FRAG_LOOP(A_, B_)                                                   \
    _Pragma("unroll")                                                           \
    for (int ks = 0; ks < HU_BK/16; ++ks) {                                     \
        int k = ks*16 + kb;                                                     \
        _Pragma("unroll")                                                       \
        for (int mi = 0; mi < 2; ++mi) {                                        \
            int r0 = mi*16 + gr;                                                \
            uint32_t a0 = *(const uint32_t*)&A_[r0*HU_ST + k];                  \
            uint32_t a1 = *(const uint32_t*)&A_[(r0+8)*HU_ST + k];              \
            uint32_t a2 = *(const uint32_t*)&A_[r0*HU_ST + k + 8];              \
            uint32_t a3 = *(const uint32_t*)&A_[(r0+8)*HU_ST + k + 8];          \
            _Pragma("unroll")                                                   \
            for (int ni = 0; ni < 2; ++ni) {                                    \
                int n = w*16 + ni*8 + gr;                                       \
                uint32_t b0 = *(const uint32_t*)&B_[n*HU_ST + k];               \
                uint32_t b1 = *(const uint32_t*)&B_[n*HU_ST + k + 8];           \
                mma_bf16(d[mi][ni], a0, a1, a2, a3, b0, b1);                    \
            }                                                                   \
        }                                                                       \
    }

#define MMA_PIPE(NCH_)                                                          \
    stage(0, 0); stage(1, 1);                                                   \
    _Pragma("unroll 1")                                                         \
    for (int ch = 0; ch < (NCH_); ++ch) {                                       \
        __syncthreads();                                                        \
        if (ch + 2 < (NCH_)) stage(ch + 2, (ch + 2) % 3);                       \
        if (ch + 2 < (NCH_)) { asm volatile("cp.async.wait_group 2;"); }        \
        else if (ch + 1 < (NCH_)) cpa_wait1();                                  \
        else cpa_wait0();                                                       \
        __syncthreads();                                                        \
        const __nv_bfloat16* A = (const __nv_bfloat16*)(sm + (ch % 3)*HU_BUF);  \
        const __nv_bfloat16* B = (const __nv_bfloat16*)(sm + (ch % 3)*HU_BUF + HU_ABUF); \
        MMA_FRAG_LOOP(A, B);                                                    \
    }

#define MMA_DECL                                                                \
    int tid = threadIdx.x;                                                      \
    int w = tid >> 5, lane = tid & 31;                                          \
    int gr = lane >> 2, kb = (lane & 3) * 2;                                    \
    float d[2][2][4];                                                           \
    _Pragma("unroll")                                                           \
    for (int mi = 0; mi < 2; ++mi)                                              \
        _Pragma("unroll")                                                       \
        for (int ni = 0; ni < 2; ++ni)                                          \
            _Pragma("unroll")                                                   \
            for (int q = 0; q < 4; ++q) d[mi][ni][q] = 0.f;

// ---------------- h_u body: D = mask @ (P1 | P2 stacked in K) -----------------------
__device__ __forceinline__ void hu_body(char* sm, int blk,
                                        const int* __restrict__ nodes_d,
                                        const float* __restrict__ dp,
                                        float* __restrict__ out_hu) {
    MMA_DECL;
    auto stage = [&](int ch, int b) {
        char* Ad = sm + b*HU_BUF;
        char* Bd = Ad + HU_ABUF;
        int k0 = ch * HU_BK;
        int split = k0 >> 10, kk = k0 & 1023;
        const char* asrc = (const char*)g_maskh4
                         + (size_t)(blk*32 + (tid >> 3))*2048 + kk*2 + (tid & 7)*16;
        cpa16(Ad + (tid >> 3)*144 + (tid & 7)*16, asrc);
        const char* bbase = (const char*)g_PB2 + ((size_t)split << 18);
        #pragma unroll
        for (int i = 0; i < 4; ++i) {
            int idx = tid + i*256; int c = idx >> 3, pc = idx & 7;
            cpa16(Bd + c*144 + pc*16, bbase + (size_t)c*2048 + kk*2 + pc*16);
        }
        cpa_commit();
    };
    MMA_PIPE(32);
    #pragma unroll
    for (int mi = 0; mi < 2; ++mi) {
        #pragma unroll
        for (int rr = 0; rr < 2; ++rr) {
            int s = blk*32 + mi*16 + gr + rr*8;
            float inv = g_cinv[s];
            const float* pdr = dp + nodes_d[s]*DD;
            #pragma unroll
            for (int ni = 0; ni < 2; ++ni) {
                int c = w*16 + ni*8 + (lane & 3)*2;
                float h0 = d[mi][ni][rr*2]   * inv;
                float h1 = d[mi][ni][rr*2+1] * inv;
                *(float2*)&out_hu[s*DD + c] = make_float2(h0, h1);
                float2 pd = *(const float2*)&pdr[c];
                uint32_t hi, lo;
                split2(h0 + pd.x, h1 + pd.y, hi, lo);
                *(uint32_t*)&g_IFB[(size_t)s*K1 + c]        = hi;
                *(uint32_t*)&g_IFB[(size_t)(BB + s)*K1 + c] = lo;
            }
        }
    }
}

// ---------------- e body: x1w1 + x1w2 + x2w1 (K_ext = 3*1152) -----------------------
__device__ __forceinline__ void e_body(char* sm, int blk,
                                       const int* __restrict__ nodes_v,
                                       const float* __restrict__ ip) {
    MMA_DECL;
    auto stage = [&](int ch, int b) {
        char* Ad = sm + b*HU_BUF;
        char* Bd = Ad + HU_ABUF;
        int seg = ch / 18;
        int kk = (ch % 18) * HU_BK;
        int sa = (seg == 2) ? 1 : 0;
        int sb = (seg == 1) ? 1 : 0;
        const char* abase = (const char*)g_XB + (size_t)sa*BB*KTOT*2;
        const char* asrc = abase + (size_t)(blk*32 + (tid >> 3))*(KTOT*2) + kk*2 + (tid & 7)*16;
        cpa16(Ad + (tid >> 3)*144 + (tid & 7)*16, asrc);
        const char* bbase = (const char*)g_WB2 + (size_t)sb*128*KTOT*2;
        #pragma unroll
        for (int i = 0; i < 4; ++i) {
            int idx = tid + i*256; int c = idx >> 3, pc = idx & 7;
            cpa16(Bd + c*144 + pc*16, bbase + (size_t)c*(KTOT*2) + kk*2 + pc*16);
        }
        cpa_commit();
    };
    MMA_PIPE(54);
    #pragma unroll
    for (int mi = 0; mi < 2; ++mi) {
        #pragma unroll
        for (int rr = 0; rr < 2; ++rr) {
            int s = blk*32 + mi*16 + gr + rr*8;
            int iv = nodes_v[s];
            #pragma unroll
            for (int ni = 0; ni < 2; ++ni) {
                int c = w*16 + ni*8 + (lane & 3)*2;
                float2 cbv = *(const float2*)&g_cb[c];
                float2 ipv = *(const float2*)&ip[(size_t)iv*DD + c];
                float e0 = d[mi][ni][rr*2]   - cbv.x + ipv.x;
                float e1 = d[mi][ni][rr*2+1] - cbv.y + ipv.y;
                uint32_t hi, lo;
                split2(e0, e1, hi, lo);
                *(uint32_t*)&g_IFB[(size_t)s*K1 + DD + c]        = hi;
                *(uint32_t*)&g_IFB[(size_t)(BB + s)*K1 + DD + c] = lo;
            }
        }
    }
}

// fused: blocks [0,128) do e, [128,256) do hu
__global__ void __launch_bounds__(256) k_eh(const int* __restrict__ nodes_v,
                                            const float* __restrict__ ip,
                                            const int* __restrict__ nodes_d,
                                            const float* __restrict__ dp,
                                            float* __restrict__ out_hu) {
    extern __shared__ char sm[];
    if (blockIdx.x < 128) e_body(sm, blockIdx.x, nodes_v, ip);
    else                  hu_body(sm, blockIdx.x - 128, nodes_d, dp, out_hu);
}

// ---------------- z1 via mma.sync: relu(IF @ W1^T + b1) + BN stats ------------------
__global__ void __launch_bounds__(256) k_z1m(const float* __restrict__ b1) {
    extern __shared__ char sm[];
    int blk = blockIdx.x;
    MMA_DECL;
    auto stage = [&](int ch, int b) {
        char* Ad = sm + b*HU_BUF;
        char* Bd = Ad + HU_ABUF;
        int seg = ch / 4;                  // 12 chunks: 3 segments x 4
        int kk = (ch % 4) * HU_BK;
        int sa = (seg == 2) ? 1 : 0;
        int sb = (seg == 1) ? 1 : 0;
        const char* abase = (const char*)g_IFB + (size_t)sa*BB*K1*2;
        const char* asrc = abase + (size_t)(blk*32 + (tid >> 3))*(K1*2) + kk*2 + (tid & 7)*16;
        cpa16(Ad + (tid >> 3)*144 + (tid & 7)*16, asrc);
        const char* bbase = (const char*)g_W1B2 + (size_t)sb*128*K1*2;
        #pragma unroll
        for (int i = 0; i < 4; ++i) {
            int idx = tid + i*256; int c = idx >> 3, pc = idx & 7;
            cpa16(Bd + c*144 + pc*16, bbase + (size_t)c*(K1*2) + kk*2 + pc*16);
        }
        cpa_commit();
    };
    MMA_PIPE(12);
    float2 bb[2];
    bb[0] = *(const float2*)&b1[w*16 + (lane & 3)*2];
    bb[1] = *(const float2*)&b1[w*16 + 8 + (lane & 3)*2];
    float ps[2][2] = {{0,0},{0,0}}, pq[2][2] = {{0,0},{0,0}};
    #pragma unroll
    for (int mi = 0; mi < 2; ++mi) {
        #pragma unroll
        for (int rr = 0; rr < 2; ++rr) {
            int s = blk*32 + mi*16 + gr + rr*8;
            #pragma unroll
            for (int ni = 0; ni < 2; ++ni) {
                int c = w*16 + ni*8 + (lane & 3)*2;
                float z0 = d[mi][ni][rr*2]   + bb[ni].x; z0 = z0 > 0.f ? z0 : 0.f;
                float z1v = d[mi][ni][rr*2+1] + bb[ni].y; z1v = z1v > 0.f ? z1v : 0.f;
                *(float2*)&g_z1[s*DD + c] = make_float2(z0, z1v);
                ps[ni][0] += z0; ps[ni][1] += z1v;
                pq[ni][0] += z0*z0; pq[ni][1] += z1v*z1v;
            }
        }
    }
    #pragma unroll
    for (int ni = 0; ni < 2; ++ni) {
        #pragma unroll
        for (int q = 0; q < 2; ++q) {
            #pragma unroll
            for (int o = 4; o <= 16; o <<= 1) {
                ps[ni][q] += __shfl_xor_sync(0xffffffffu, ps[ni][q], o);
                pq[ni][q] += __shfl_xor_sync(0xffffffffu, pq[ni][q], o);
            }
        }
        if (lane < 4) {
            int c = w*16 + ni*8 + lane*2;
            atomicAdd(&g_s1[c],   ps[ni][0]); atomicAdd(&g_s1[c+1], ps[ni][1]);
            atomicAdd(&g_q1[c],   pq[ni][0]); atomicAdd(&g_q1[c+1], pq[ni][1]);
        }
    }
}

// ---------------- z2 = relu(BN(z1) @ W2^T + b2) + partial BN stats (fold inline) ----
__global__ void __launch_bounds__(128) k_z2(const float* __restrict__ b2,
                                            const float* __restrict__ g1,
                                            const float* __restrict__ be1) {
    __shared__ __align__(16) float2 W2s[(DD/2)*D2];  // 32KB
    __shared__ __align__(16) float X[ESG][DD];       // 8KB
    __shared__ float A1[DD], D1[DD];
    int blk = blockIdx.x, tid = threadIdx.x;
    int c = tid & 63, h = tid >> 6;
    {
        const float4* src = (const float4*)g_W2T2;
        float4* dst = (float4*)W2s;
        #pragma unroll
        for (int i = 0; i < 16; ++i)
            cpa16(dst + tid + i*128, src + tid + i*128);
        cpa_commit();
    }
    if (tid < DD) {
        float m = g_s1[tid] * (1.0f/BB);
        float v = g_q1[tid] * (1.0f/BB) - m*m;
        float r = rsqrtf(v + 1e-5f);
        float a = g1[tid] * r;
        A1[tid] = a;
        D1[tid] = be1[tid] - m*a;
    }
    __syncthreads();
    for (int l = tid; l < ESG*DD; l += 128) {
        int s = l >> 7, kk = l & 127;
        X[s][kk] = g_z1[(blk*ESG + s)*DD + kk] * A1[kk] + D1[kk];
    }
    cpa_wait0();
    __syncthreads();
    ull acc[8];
    #pragma unroll
    for (int i = 0; i < 8; ++i) acc[i] = 0ull;
    #pragma unroll 8
    for (int p = 0; p < DD/2; ++p) {
        ull wv = *(const ull*)&W2s[p*D2 + c];
        #pragma unroll
        for (int i = 0; i < 8; ++i) {
            ull x = *(const ull*)&X[h*8 + i][2*p];
            ffma2(acc[i], wv, x);
        }
    }
    float bb = b2[c];
    float lsum = 0.f, lss = 0.f;
    #pragma unroll
    for (int i = 0; i < 8; ++i) {
        float z = sum2(acc[i]) + bb;
        z = z > 0.f ? z : 0.f;
        g_z2[(blk*ESG + h*8 + i)*D2 + c] = z;
        lsum += z; lss += z*z;
    }
    atomicAdd(&g_s2[c], lsum);
    atomicAdd(&g_q2[c], lss);
}

// ---------------- pred = sigmoid(BN(z2) @ Wp^T + bp), BN fold inline ---------------
__global__ void k_pred(const float* __restrict__ Wp, const float* __restrict__ bp,
                       const float* __restrict__ g2, const float* __restrict__ be2,
                       float* __restrict__ out_pred) {
    __shared__ float A2[D2], D2v[D2];
    int tid = threadIdx.x;
    if (tid < D2) {
        float m = g_s2[tid] * (1.0f/BB);
        float v = g_q2[tid] * (1.0f/BB) - m*m;
        float r = rsqrtf(v + 1e-5f);
        float a = g2[tid] * r;
        A2[tid] = a;
        D2v[tid] = be2[tid] - m*a;
    }
    __syncthreads();
    int warp = (blockIdx.x*blockDim.x + tid) >> 5;
    int lane = tid & 31;
    if (warp >= BB) return;
    float t = 0.f;
    #pragma unroll
    for (int j = 0; j < 2; ++j) {
        int cidx = lane + j*32;
        float f2 = g_z2[warp*D2 + cidx] * A2[cidx] + D2v[cidx];
        t += f2 * Wp[cidx];
    }
    #pragma unroll
    for (int o = 16; o; o >>= 1) t += __shfl_down_sync(0xffffffffu, t, o);
    if (lane == 0) out_pred[warp] = 1.0f / (1.0f + expf(-(t + bp[0])));
}

// ---------------- launch ------------------------------------------------------------
extern "C" void kernel_launch(void* const* d_in, const int* in_sizes, int n_in,
                              void* d_out, int out_size) {
    const int*   nodes_u     = (const int*)  d_in[0];
    const int*   nodes_v     = (const int*)  d_in[1];
    const int*   nodes_d     = (const int*)  d_in[2];
    const int*   inter_items = (const int*)  d_in[3];
    const int*   top_n       = (const int*)  d_in[4];
    const float* protos      = (const float*)d_in[5];
    const float* pre_text    = (const float*)d_in[6];
    const float* pre_visual  = (const float*)d_in[7];
    const float* Wt          = (const float*)d_in[8];
    const float* bt          = (const float*)d_in[9];
    const float* Wv          = (const float*)d_in[10];
    const float* bv          = (const float*)d_in[11];
    const float* up          = (const float*)d_in[12];
    const float* ip          = (const float*)d_in[13];
    const float* dp          = (const float*)d_in[14];
    const float* W1          = (const float*)d_in[15];
    const float* b1          = (const float*)d_in[16];
    const float* g1          = (const float*)d_in[17];
    const float* be1         = (const float*)d_in[18];
    const float* W2          = (const float*)d_in[19];
    const float* b2          = (const float*)d_in[20];
    const float* g2          = (const float*)d_in[21];
    const float* be2         = (const float*)d_in[22];
    const float* Wp          = (const float*)d_in[23];
    const float* bp          = (const float*)d_in[24];

    float* out      = (float*)d_out;
    float* out_pred = out;
    float* out_pu   = out + BB;
    float* out_hu   = out + BB + BB*DD;
    float* out_pd   = out + BB + 2*BB*DD;

    cudaFuncSetAttribute(k_eh,  cudaFuncAttributeMaxDynamicSharedMemorySize, HU_SMEM);
    cudaFuncSetAttribute(k_z1m, cudaFuncAttributeMaxDynamicSharedMemorySize, HU_SMEM);

    k_prep<<<312, 256>>>(Wt, Wv, W1, W2, protos, bt, bv);
    k_xbm<<<BB, 288>>>(nodes_u, nodes_v, nodes_d, inter_items, top_n,
                       pre_text, pre_visual, up, dp, out_pu, out_pd);
    k_eh<<<256, 256, HU_SMEM>>>(nodes_v, ip, nodes_d, dp, out_hu);
    k_z1m<<<BB/32, 256, HU_SMEM>>>(b1);
    k_z2<<<BB/ESG, 128>>>(b2, g1, be1);
    k_pred<<<BB/8, 256>>>(Wp, bp, g2, be2, out_pred);
}

// round 12
// speedup vs baseline: 1.1004x; 1.0109x over previous
#include <cuda_runtime.h>
#include <cuda_bf16.h>
#include <cstdint>

// Problem constants
#define BB    4096
#define DD    128
#define HIST  50
#define TOPN  4
#define PROTO 1024
#define ITEMS 100000
#define KTOT  1152      // 384 text + 768 visual
#define K1    256       // MLP layer1 input
#define D2    64        // MLP layer2 output
#define ESG   16        // samples per z2 block

typedef unsigned long long ull;

// ---------------- scratch (__device__ globals; no allocation allowed) ----------------
__device__ float2 g_W2T2[(DD/2)*D2];
__device__ float  g_cb[DD];             // bt·Wt_row + bv·Wv_row
__device__ uint4  g_maskh4[BB*PROTO/8]; // bf16 0/1 presence mask (8MB)
__device__ __align__(16) __nv_bfloat16 g_PB2[2*128*1024];  // bf16 split protos^T [split][c][k]
__device__ __align__(16) __nv_bfloat16 g_WB2[2*128*KTOT];  // bf16 split [Wt|Wv]  [split][c][k]
__device__ __align__(16) __nv_bfloat16 g_W1B2[2*128*K1];   // bf16 split W1       [split][c][k]
__device__ __align__(16) __nv_bfloat16 g_XB[2*BB*KTOT];    // bf16 split gathered features
__device__ __align__(16) __nv_bfloat16 g_IFB[2*BB*K1];     // bf16 split inter_feat
__device__ float  g_cinv[BB];           // 1/unique-count
__device__ float  g_z1[BB*DD];
__device__ float  g_z2[BB*D2];
__device__ float  g_s1[DD], g_q1[DD];
__device__ float  g_s2[D2], g_q2[D2];

__device__ __forceinline__ void ffma2(ull &acc, ull a, ull b) {
    asm("fma.rn.f32x2 %0, %1, %2, %0;" : "+l"(acc) : "l"(a), "l"(b));
}
__device__ __forceinline__ float sum2(ull v) {
    return __uint_as_float((unsigned)v) + __uint_as_float((unsigned)(v >> 32));
}
__device__ __forceinline__ void cpa16(void* dst, const void* src) {
    unsigned d = (unsigned)__cvta_generic_to_shared(dst);
    asm volatile("cp.async.cg.shared.global [%0], [%1], 16;" :: "r"(d), "l"(src));
}
__device__ __forceinline__ void cpa_commit() { asm volatile("cp.async.commit_group;"); }
__device__ __forceinline__ void cpa_wait1() { asm volatile("cp.async.wait_group 1;"); }
__device__ __forceinline__ void cpa_wait0() { asm volatile("cp.async.wait_group 0;"); }

// HMMA bf16: D(f32) += A(bf16 m16k16 row) * B(bf16 k16n8 col)
__device__ __forceinline__ void mma_bf16(float* d, uint32_t a0, uint32_t a1,
                                         uint32_t a2, uint32_t a3,
                                         uint32_t b0, uint32_t b1) {
    asm volatile("mma.sync.aligned.m16n8k16.row.col.f32.bf16.bf16.f32 "
                 "{%0,%1,%2,%3},{%4,%5,%6,%7},{%8,%9},{%0,%1,%2,%3};"
                 : "+f"(d[0]), "+f"(d[1]), "+f"(d[2]), "+f"(d[3])
                 : "r"(a0), "r"(a1), "r"(a2), "r"(a3), "r"(b0), "r"(b1));
}
__device__ __forceinline__ uint32_t pk_bf2(float lo, float hi) {
    uint32_t r;
    asm("cvt.rn.bf16x2.f32 %0, %1, %2;" : "=r"(r) : "f"(hi), "f"(lo));
    return r;
}
__device__ __forceinline__ void split2(float v0, float v1, uint32_t &hi, uint32_t &lo) {
    __nv_bfloat16 h0 = __float2bfloat16(v0), h1 = __float2bfloat16(v1);
    uint16_t u0, u1; memcpy(&u0, &h0, 2); memcpy(&u1, &h1, 2);
    hi = (uint32_t)u0 | ((uint32_t)u1 << 16);
    lo = pk_bf2(v0 - __bfloat162float(h0), v1 - __bfloat162float(h1));
}

// ---------------- prep: weight splits/layouts + zero stats + cb ---------------------
__global__ void k_prep(const float* __restrict__ Wt, const float* __restrict__ Wv,
                       const float* __restrict__ W1, const float* __restrict__ W2,
                       const float* __restrict__ protos,
                       const float* __restrict__ bt, const float* __restrict__ bv) {
    int tid = threadIdx.x;
    if (blockIdx.x >= 296) {   // cb part: 16 blocks x 8 warps = 128 columns
        int c = (blockIdx.x - 296)*8 + (tid >> 5);
        int l = tid & 31;
        float s = 0.f;
        for (int k = l; k < 384; k += 32) s += bt[k] * Wt[c*384 + k];
        for (int k = l; k < 768; k += 32) s += bv[k] * Wv[c*768 + k];
        #pragma unroll
        for (int o = 16; o; o >>= 1) s += __shfl_down_sync(0xffffffffu, s, o);
        if (l == 0) g_cb[c] = s;
        return;
    }
    const int n_wb = 128*KTOT;
    const int n_pb = 128*1024;
    const int n_w1 = 128*K1;
    const int n_w2 = (DD/2)*D2;
    const int n_z  = 2*DD + 2*D2;
    int total = n_wb + n_pb + n_w1 + n_w2 + n_z;
    for (int i = blockIdx.x*blockDim.x + tid; i < total; i += 296*blockDim.x) {
        if (i < n_wb) {
            int c = i / KTOT, k = i % KTOT;
            float v = (k < 384) ? Wt[c*384 + k] : Wv[c*768 + (k - 384)];
            __nv_bfloat16 b1 = __float2bfloat16(v);
            g_WB2[i]            = b1;
            g_WB2[128*KTOT + i] = __float2bfloat16(v - __bfloat162float(b1));
        } else if (i < n_wb + n_pb) {
            int j = i - n_wb; int c = j & 127; int k = j >> 7;
            float p = protos[k*DD + c];
            __nv_bfloat16 b1 = __float2bfloat16(p);
            g_PB2[c*1024 + k]          = b1;
            g_PB2[131072 + c*1024 + k] = __float2bfloat16(p - __bfloat162float(b1));
        } else if (i < n_wb + n_pb + n_w1) {
            int j = i - n_wb - n_pb;
            float v = W1[j];
            __nv_bfloat16 b1 = __float2bfloat16(v);
            g_W1B2[j]          = b1;
            g_W1B2[128*K1 + j] = __float2bfloat16(v - __bfloat162float(b1));
        } else if (i < n_wb + n_pb + n_w1 + n_w2) {
            int j = i - n_wb - n_pb - n_w1; int k2 = j / D2, c = j % D2;
            g_W2T2[j] = make_float2(W2[c*DD + 2*k2], W2[c*DD + 2*k2 + 1]);
        } else {
            int j = i - n_wb - n_pb - n_w1 - n_w2;
            if (j < DD)            g_s1[j] = 0.f;
            else if (j < 2*DD)     g_q1[j-DD] = 0.f;
            else if (j < 2*DD+D2)  g_s2[j-2*DD] = 0.f;
            else                   g_q2[j-2*DD-D2] = 0.f;
        }
    }
}

// ---------------- fused: feature gather/split + mask build + prompt gathers ---------
__global__ void __launch_bounds__(288) k_xbm(
        const int* __restrict__ nodes_u, const int* __restrict__ nodes_v,
        const int* __restrict__ nodes_d, const int* __restrict__ inter_items,
        const int* __restrict__ top_n,
        const float* __restrict__ pre_text, const float* __restrict__ pre_visual,
        const float* __restrict__ up, const float* __restrict__ dp,
        float* __restrict__ out_pu, float* __restrict__ out_pd) {
    __shared__ unsigned bm[PROTO/32];
    int s = blockIdx.x, tid = threadIdx.x;
    int row = nodes_v[s];
    float4 v = (tid < 96) ? ((const float4*)(pre_text + (size_t)row*384))[tid]
                          : ((const float4*)(pre_visual + (size_t)row*768))[tid - 96];
    if (tid < 32) bm[tid] = 0u;
    __syncthreads();
    if (tid < HIST) {
        int item = inter_items[s*HIST + tid];
        int4 r1 = ((const int4*)top_n)[item];
        int4 r2 = ((const int4*)top_n)[item + ITEMS];
        atomicOr(&bm[r1.x >> 5], 1u << (r1.x & 31));
        atomicOr(&bm[r1.y >> 5], 1u << (r1.y & 31));
        atomicOr(&bm[r1.z >> 5], 1u << (r1.z & 31));
        atomicOr(&bm[r1.w >> 5], 1u << (r1.w & 31));
        atomicOr(&bm[r2.x >> 5], 1u << (r2.x & 31));
        atomicOr(&bm[r2.y >> 5], 1u << (r2.y & 31));
        atomicOr(&bm[r2.z >> 5], 1u << (r2.z & 31));
        atomicOr(&bm[r2.w >> 5], 1u << (r2.w & 31));
    }
    {
        uint32_t h0, l0, h1, l1;
        split2(v.x, v.y, h0, l0);
        split2(v.z, v.w, h1, l1);
        size_t off = (size_t)s*KTOT + 4*tid;
        *(uint2*)(g_XB + off)                   = make_uint2(h0, h1);
        *(uint2*)(g_XB + (size_t)BB*KTOT + off) = make_uint2(l0, l1);
    }
    __syncthreads();
    if (tid < 32) {
        unsigned c = __popc(bm[tid]);
        #pragma unroll
        for (int o = 16; o; o >>= 1) c += __shfl_down_sync(0xffffffffu, c, o);
        if (tid == 0) g_cinv[s] = 1.0f / (float)c;
    }
    if (tid < 128) {
        unsigned w = bm[tid >> 2];
        int sh = (tid & 3) * 8;
        uint32_t pk[4];
        #pragma unroll
        for (int q = 0; q < 4; ++q) {
            uint32_t lo = ((w >> (sh + 2*q)) & 1) ? 0x3F80u : 0u;
            uint32_t hi = ((w >> (sh + 2*q + 1)) & 1) ? 0x3F80u : 0u;
            pk[q] = lo | (hi << 16);
        }
        g_maskh4[(size_t)s*128 + tid] = make_uint4(pk[0], pk[1], pk[2], pk[3]);
        out_pu[s*DD + tid] = up[nodes_u[s]*DD + tid];
        out_pd[s*DD + tid] = dp[nodes_d[s]*DD + tid];
    }
}

// ===================================================================================
// HMMA GEMM skeleton (M=32): 256 thr; per CTA M=32 samples, N=128 cols, BK=64.
// smem row stride 72 bf16 (144B). Warp w covers cols [w*16, w*16+16).
// ===================================================================================
#define HU_BK   64
#define HU_ST   72
#define HU_ABUF (32*HU_ST*2)
#define HU_BBUF (128*HU_ST*2)
#define HU_BUF  (HU_ABUF + HU_BBUF)
#define HU_SMEM (3*HU_BUF)          // 69120 B

#define MMA_FRAG_LOOP(A_, B_)                                                   \
    _Pragma("unroll")                                                           \
    for (int ks = 0; ks < HU_BK/16; ++ks) {                                     \
        int k = ks*16 + kb;                                                     \
        _Pragma("unroll")                                                       \
        for (int mi = 0; mi < 2; ++mi) {                                        \
            int r0 = mi*16 + gr;                                                \
            uint32_t a0 = *(const uint32_t*)&A_[r0*HU_ST + k];                  \
            uint32_t a1 = *(const uint32_t*)&A_[(r0+8)*HU_ST + k];              \
            uint32_t a2 = *(const uint32_t*)&A_[r0*HU_ST + k + 8];              \
            uint32_t a3 = *(const uint32_t*)&A_[(r0+8)*HU_ST + k + 8];          \
            _Pragma("unroll")                                                   \
            for (int ni = 0; ni < 2; ++ni) {                                    \
                int n = w*16 + ni*8 + gr;                                       \
                uint32_t b0 = *(const uint32_t*)&B_[n*HU_ST + k];               \
                uint32_t b1 = *(const uint32_t*)&B_[n*HU_ST + k + 8];           \
                mma_bf16(d[mi][ni], a0, a1, a2, a3, b0, b1);                    \
            }                                                                   \
        }                                                                       \
    }

#define MMA_PIPE(NCH_)                                                          \
    stage(0, 0); stage(1, 1);                                                   \
    _Pragma("unroll 1")                                                         \
    for (int ch = 0; ch < (NCH_); ++ch) {                                       \
        __syncthreads();                                                        \
        if (ch + 2 < (NCH_)) stage(ch + 2, (ch + 2) % 3);                       \
        if (ch + 2 < (NCH_)) { asm volatile("cp.async.wait_group 2;"); }        \
        else if (ch + 1 < (NCH_)) cpa_wait1();                                  \
        else cpa_wait0();                                                       \
        __syncthreads();                                                        \
        const __nv_bfloat16* A = (const __nv_bfloat16*)(sm + (ch % 3)*HU_BUF);  \
        const __nv_bfloat16* B = (const __nv_bfloat16*)(sm + (ch % 3)*HU_BUF + HU_ABUF); \
        MMA_FRAG_LOOP(A, B);                                                    \
    }

#define MMA_DECL                                                                \
    int tid = threadIdx.x;                                                      \
    int w = tid >> 5, lane = tid & 31;                                          \
    int gr = lane >> 2, kb = (lane & 3) * 2;                                    \
    float d[2][2][4];                                                           \
    _Pragma("unroll")                                                           \
    for (int mi = 0; mi < 2; ++mi)                                              \
        _Pragma("unroll")                                                       \
        for (int ni = 0; ni < 2; ++ni)                                          \
            _Pragma("unroll")                                                   \
            for (int q = 0; q < 4; ++q) d[mi][ni][q] = 0.f;

// ---------------- h_u body: D = mask @ (P1 | P2 stacked in K) -----------------------
__device__ __forceinline__ void hu_body(char* sm, int blk,
                                        const int* __restrict__ nodes_d,
                                        const float* __restrict__ dp,
                                        float* __restrict__ out_hu) {
    MMA_DECL;
    auto stage = [&](int ch, int b) {
        char* Ad = sm + b*HU_BUF;
        char* Bd = Ad + HU_ABUF;
        int k0 = ch * HU_BK;
        int split = k0 >> 10, kk = k0 & 1023;
        const char* asrc = (const char*)g_maskh4
                         + (size_t)(blk*32 + (tid >> 3))*2048 + kk*2 + (tid & 7)*16;
        cpa16(Ad + (tid >> 3)*144 + (tid & 7)*16, asrc);
        const char* bbase = (const char*)g_PB2 + ((size_t)split << 18);
        #pragma unroll
        for (int i = 0; i < 4; ++i) {
            int idx = tid + i*256; int c = idx >> 3, pc = idx & 7;
            cpa16(Bd + c*144 + pc*16, bbase + (size_t)c*2048 + kk*2 + pc*16);
        }
        cpa_commit();
    };
    MMA_PIPE(32);
    #pragma unroll
    for (int mi = 0; mi < 2; ++mi) {
        #pragma unroll
        for (int rr = 0; rr < 2; ++rr) {
            int s = blk*32 + mi*16 + gr + rr*8;
            float inv = g_cinv[s];
            const float* pdr = dp + nodes_d[s]*DD;
            #pragma unroll
            for (int ni = 0; ni < 2; ++ni) {
                int c = w*16 + ni*8 + (lane & 3)*2;
                float h0 = d[mi][ni][rr*2]   * inv;
                float h1 = d[mi][ni][rr*2+1] * inv;
                *(float2*)&out_hu[s*DD + c] = make_float2(h0, h1);
                float2 pd = *(const float2*)&pdr[c];
                uint32_t hi, lo;
                split2(h0 + pd.x, h1 + pd.y, hi, lo);
                *(uint32_t*)&g_IFB[(size_t)s*K1 + c]        = hi;
                *(uint32_t*)&g_IFB[(size_t)(BB + s)*K1 + c] = lo;
            }
        }
    }
}

// ---------------- e body: x1w1 + x1w2 + x2w1 (K_ext = 3*1152) -----------------------
__device__ __forceinline__ void e_body(char* sm, int blk,
                                       const int* __restrict__ nodes_v,
                                       const float* __restrict__ ip) {
    MMA_DECL;
    auto stage = [&](int ch, int b) {
        char* Ad = sm + b*HU_BUF;
        char* Bd = Ad + HU_ABUF;
        int seg = ch / 18;
        int kk = (ch % 18) * HU_BK;
        int sa = (seg == 2) ? 1 : 0;
        int sb = (seg == 1) ? 1 : 0;
        const char* abase = (const char*)g_XB + (size_t)sa*BB*KTOT*2;
        const char* asrc = abase + (size_t)(blk*32 + (tid >> 3))*(KTOT*2) + kk*2 + (tid & 7)*16;
        cpa16(Ad + (tid >> 3)*144 + (tid & 7)*16, asrc);
        const char* bbase = (const char*)g_WB2 + (size_t)sb*128*KTOT*2;
        #pragma unroll
        for (int i = 0; i < 4; ++i) {
            int idx = tid + i*256; int c = idx >> 3, pc = idx & 7;
            cpa16(Bd + c*144 + pc*16, bbase + (size_t)c*(KTOT*2) + kk*2 + pc*16);
        }
        cpa_commit();
    };
    MMA_PIPE(54);
    #pragma unroll
    for (int mi = 0; mi < 2; ++mi) {
        #pragma unroll
        for (int rr = 0; rr < 2; ++rr) {
            int s = blk*32 + mi*16 + gr + rr*8;
            int iv = nodes_v[s];
            #pragma unroll
            for (int ni = 0; ni < 2; ++ni) {
                int c = w*16 + ni*8 + (lane & 3)*2;
                float2 cbv = *(const float2*)&g_cb[c];
                float2 ipv = *(const float2*)&ip[(size_t)iv*DD + c];
                float e0 = d[mi][ni][rr*2]   - cbv.x + ipv.x;
                float e1 = d[mi][ni][rr*2+1] - cbv.y + ipv.y;
                uint32_t hi, lo;
                split2(e0, e1, hi, lo);
                *(uint32_t*)&g_IFB[(size_t)s*K1 + DD + c]        = hi;
                *(uint32_t*)&g_IFB[(size_t)(BB + s)*K1 + DD + c] = lo;
            }
        }
    }
}

// fused: blocks [0,128) do e, [128,256) do hu
__global__ void __launch_bounds__(256) k_eh(const int* __restrict__ nodes_v,
                                            const float* __restrict__ ip,
                                            const int* __restrict__ nodes_d,
                                            const float* __restrict__ dp,
                                            float* __restrict__ out_hu) {
    extern __shared__ char sm[];
    if (blockIdx.x < 128) e_body(sm, blockIdx.x, nodes_v, ip);
    else                  hu_body(sm, blockIdx.x - 128, nodes_d, dp, out_hu);
}

// ---------------- z1 via mma.sync, FULL-STAGE variant -------------------------------
// All of A (IFB rows, both splits: 32KB) and B (W1 both splits: 128KB) staged in one
// cp.async burst; ONE barrier; then all 12 K-chunks back-to-back (no further syncs).
// Row stride 264 bf16 (528B): (132 words mod 32 = 4) -> conflict-free frag loads.
#define Z1_ST    264
#define Z1_ROWB  528
#define Z1_AOFF  0
#define Z1_BOFF  (64*Z1_ROWB)                 // 33792
#define Z1_SMEM  (64*Z1_ROWB + 256*Z1_ROWB)   // 168960 B

__global__ void __launch_bounds__(256) k_z1m(const float* __restrict__ b1) {
    extern __shared__ char sm[];
    int blk = blockIdx.x;
    MMA_DECL;
    // bulk stage: A rows = [sa*32 + r] (64 rows x 512B), B rows = [sb*128 + c] (256 x 512B)
    {
        // A: 64 rows x 32 16B-chunks = 2048 transfers (8/thread)
        #pragma unroll
        for (int i = 0; i < 8; ++i) {
            int idx = tid + i*256;           // 0..2047
            int r = idx >> 5, pc = idx & 31; // row (sa*32+smp), 16B chunk
            int sa = r >> 5, smp = r & 31;
            const char* src = (const char*)g_IFB + (size_t)sa*BB*K1*2
                            + (size_t)(blk*32 + smp)*(K1*2) + pc*16;
            cpa16(sm + Z1_AOFF + r*Z1_ROWB + pc*16, src);
        }
        // B: 256 rows x 32 chunks = 8192 transfers (32/thread)
        #pragma unroll
        for (int i = 0; i < 32; ++i) {
            int idx = tid + i*256;           // 0..8191
            int r = idx >> 5, pc = idx & 31; // row (sb*128+c)
            const char* src = (const char*)g_W1B2 + (size_t)r*(K1*2) + pc*16;
            cpa16(sm + Z1_BOFF + r*Z1_ROWB + pc*16, src);
        }
        cpa_commit();
    }
    cpa_wait0();
    __syncthreads();
    // 12 chunks: seg in {0:(hi,hi), 1:(hi,lo), 2:(lo,hi)} x 4 k-chunks of 64
    #pragma unroll 1
    for (int ch = 0; ch < 12; ++ch) {
        int seg = ch >> 2;
        int k0 = (ch & 3) * HU_BK;
        int sa = (seg == 2) ? 1 : 0;
        int sb = (seg == 1) ? 1 : 0;
        const __nv_bfloat16* A = (const __nv_bfloat16*)(sm + Z1_AOFF + sa*32*Z1_ROWB) + k0;
        const __nv_bfloat16* B = (const __nv_bfloat16*)(sm + Z1_BOFF + sb*128*Z1_ROWB) + k0;
        #pragma unroll
        for (int ks = 0; ks < HU_BK/16; ++ks) {
            int k = ks*16 + kb;
            #pragma unroll
            for (int mi = 0; mi < 2; ++mi) {
                int r0 = mi*16 + gr;
                uint32_t a0 = *(const uint32_t*)&A[r0*Z1_ST + k];
                uint32_t a1 = *(const uint32_t*)&A[(r0+8)*Z1_ST + k];
                uint32_t a2 = *(const uint32_t*)&A[r0*Z1_ST + k + 8];
                uint32_t a3 = *(const uint32_t*)&A[(r0+8)*Z1_ST + k + 8];
                #pragma unroll
                for (int ni = 0; ni < 2; ++ni) {
                    int n = w*16 + ni*8 + gr;
                    uint32_t b0 = *(const uint32_t*)&B[n*Z1_ST + k];
                    uint32_t b1v = *(const uint32_t*)&B[n*Z1_ST + k + 8];
                    mma_bf16(d[mi][ni], a0, a1, a2, a3, b0, b1v);
                }
            }
        }
    }
    float2 bb[2];
    bb[0] = *(const float2*)&b1[w*16 + (lane & 3)*2];
    bb[1] = *(const float2*)&b1[w*16 + 8 + (lane & 3)*2];
    float ps[2][2] = {{0,0},{0,0}}, pq[2][2] = {{0,0},{0,0}};
    #pragma unroll
    for (int mi = 0; mi < 2; ++mi) {
        #pragma unroll
        for (int rr = 0; rr < 2; ++rr) {
            int s = blk*32 + mi*16 + gr + rr*8;
            #pragma unroll
            for (int ni = 0; ni < 2; ++ni) {
                int c = w*16 + ni*8 + (lane & 3)*2;
                float z0 = d[mi][ni][rr*2]   + bb[ni].x; z0 = z0 > 0.f ? z0 : 0.f;
                float z1v = d[mi][ni][rr*2+1] + bb[ni].y; z1v = z1v > 0.f ? z1v : 0.f;
                *(float2*)&g_z1[s*DD + c] = make_float2(z0, z1v);
                ps[ni][0] += z0; ps[ni][1] += z1v;
                pq[ni][0] += z0*z0; pq[ni][1] += z1v*z1v;
            }
        }
    }
    #pragma unroll
    for (int ni = 0; ni < 2; ++ni) {
        #pragma unroll
        for (int q = 0; q < 2; ++q) {
            #pragma unroll
            for (int o = 4; o <= 16; o <<= 1) {
                ps[ni][q] += __shfl_xor_sync(0xffffffffu, ps[ni][q], o);
                pq[ni][q] += __shfl_xor_sync(0xffffffffu, pq[ni][q], o);
            }
        }
        if (lane < 4) {
            int c = w*16 + ni*8 + lane*2;
            atomicAdd(&g_s1[c],   ps[ni][0]); atomicAdd(&g_s1[c+1], ps[ni][1]);
            atomicAdd(&g_q1[c],   pq[ni][0]); atomicAdd(&g_q1[c+1], pq[ni][1]);
        }
    }
}

// ---------------- z2 = relu(BN(z1) @ W2^T + b2) + partial BN stats (fold inline) ----
__global__ void __launch_bounds__(128) k_z2(const float* __restrict__ b2,
                                            const float* __restrict__ g1,
                                            const float* __restrict__ be1) {
    __shared__ __align__(16) float2 W2s[(DD/2)*D2];  // 32KB
    __shared__ __align__(16) float X[ESG][DD];       // 8KB
    __shared__ float A1[DD], D1[DD];
    int blk = blockIdx.x, tid = threadIdx.x;
    int c = tid & 63, h = tid >> 6;
    {
        const float4* src = (const float4*)g_W2T2;
        float4* dst = (float4*)W2s;
        #pragma unroll
        for (int i = 0; i < 16; ++i)
            cpa16(dst + tid + i*128, src + tid + i*128);
        cpa_commit();
    }
    if (tid < DD) {
        float m = g_s1[tid] * (1.0f/BB);
        float v = g_q1[tid] * (1.0f/BB) - m*m;
        float r = rsqrtf(v + 1e-5f);
        float a = g1[tid] * r;
        A1[tid] = a;
        D1[tid] = be1[tid] - m*a;
    }
    __syncthreads();
    for (int l = tid; l < ESG*DD; l += 128) {
        int s = l >> 7, kk = l & 127;
        X[s][kk] = g_z1[(blk*ESG + s)*DD + kk] * A1[kk] + D1[kk];
    }
    cpa_wait0();
    __syncthreads();
    ull acc[8];
    #pragma unroll
    for (int i = 0; i < 8; ++i) acc[i] = 0ull;
    #pragma unroll 8
    for (int p = 0; p < DD/2; ++p) {
        ull wv = *(const ull*)&W2s[p*D2 + c];
        #pragma unroll
        for (int i = 0; i < 8; ++i) {
            ull x = *(const ull*)&X[h*8 + i][2*p];
            ffma2(acc[i], wv, x);
        }
    }
    float bb = b2[c];
    float lsum = 0.f, lss = 0.f;
    #pragma unroll
    for (int i = 0; i < 8; ++i) {
        float z = sum2(acc[i]) + bb;
        z = z > 0.f ? z : 0.f;
        g_z2[(blk*ESG + h*8 + i)*D2 + c] = z;
        lsum += z; lss += z*z;
    }
    atomicAdd(&g_s2[c], lsum);
    atomicAdd(&g_q2[c], lss);
}

// ---------------- pred = sigmoid(BN(z2) @ Wp^T + bp), BN fold inline ---------------
__global__ void k_pred(const float* __restrict__ Wp, const float* __restrict__ bp,
                       const float* __restrict__ g2, const float* __restrict__ be2,
                       float* __restrict__ out_pred) {
    __shared__ float A2[D2], D2v[D2];
    int tid = threadIdx.x;
    if (tid < D2) {
        float m = g_s2[tid] * (1.0f/BB);
        float v = g_q2[tid] * (1.0f/BB) - m*m;
        float r = rsqrtf(v + 1e-5f);
        float a = g2[tid] * r;
        A2[tid] = a;
        D2v[tid] = be2[tid] - m*a;
    }
    __syncthreads();
    int warp = (blockIdx.x*blockDim.x + tid) >> 5;
    int lane = tid & 31;
    if (warp >= BB) return;
    float t = 0.f;
    #pragma unroll
    for (int j = 0; j < 2; ++j) {
        int cidx = lane + j*32;
        float f2 = g_z2[warp*D2 + cidx] * A2[cidx] + D2v[cidx];
        t += f2 * Wp[cidx];
    }
    #pragma unroll
    for (int o = 16; o; o >>= 1) t += __shfl_down_sync(0xffffffffu, t, o);
    if (lane == 0) out_pred[warp] = 1.0f / (1.0f + expf(-(t + bp[0])));
}

// ---------------- launch ------------------------------------------------------------
extern "C" void kernel_launch(void* const* d_in, const int* in_sizes, int n_in,
                              void* d_out, int out_size) {
    const int*   nodes_u     = (const int*)  d_in[0];
    const int*   nodes_v     = (const int*)  d_in[1];
    const int*   nodes_d     = (const int*)  d_in[2];
    const int*   inter_items = (const int*)  d_in[3];
    const int*   top_n       = (const int*)  d_in[4];
    const float* protos      = (const float*)d_in[5];
    const float* pre_text    = (const float*)d_in[6];
    const float* pre_visual  = (const float*)d_in[7];
    const float* Wt          = (const float*)d_in[8];
    const float* bt          = (const float*)d_in[9];
    const float* Wv          = (const float*)d_in[10];
    const float* bv          = (const float*)d_in[11];
    const float* up          = (const float*)d_in[12];
    const float* ip          = (const float*)d_in[13];
    const float* dp          = (const float*)d_in[14];
    const float* W1          = (const float*)d_in[15];
    const float* b1          = (const float*)d_in[16];
    const float* g1          = (const float*)d_in[17];
    const float* be1         = (const float*)d_in[18];
    const float* W2          = (const float*)d_in[19];
    const float* b2          = (const float*)d_in[20];
    const float* g2          = (const float*)d_in[21];
    const float* be2         = (const float*)d_in[22];
    const float* Wp          = (const float*)d_in[23];
    const float* bp          = (const float*)d_in[24];

    float* out      = (float*)d_out;
    float* out_pred = out;
    float* out_pu   = out + BB;
    float* out_hu   = out + BB + BB*DD;
    float* out_pd   = out + BB + 2*BB*DD;

    cudaFuncSetAttribute(k_eh,  cudaFuncAttributeMaxDynamicSharedMemorySize, HU_SMEM);
    cudaFuncSetAttribute(k_z1m, cudaFuncAttributeMaxDynamicSharedMemorySize, Z1_SMEM);

    k_prep<<<312, 256>>>(Wt, Wv, W1, W2, protos, bt, bv);
    k_xbm<<<BB, 288>>>(nodes_u, nodes_v, nodes_d, inter_items, top_n,
                       pre_text, pre_visual, up, dp, out_pu, out_pd);
    k_eh<<<256, 256, HU_SMEM>>>(nodes_v, ip, nodes_d, dp, out_hu);
    k_z1m<<<BB/32, 256, Z1_SMEM>>>(b1);
    k_z2<<<BB/ESG, 128>>>(b2, g1, be1);
    k_pred<<<BB/8, 256>>>(Wp, bp, g2, be2, out_pred);
}

// round 13
// speedup vs baseline: 1.2862x; 1.1689x over previous
#include <cuda_runtime.h>
#include <cuda_bf16.h>
#include <cstdint>

// Problem constants
#define BB    4096
#define DD    128
#define HIST  50
#define TOPN  4
#define PROTO 1024
#define ITEMS 100000
#define KTOT  1152      // 384 text + 768 visual
#define K1    256       // MLP layer1 input
#define D2    64        // MLP layer2 output
#define ESG   16        // samples per z2 block

typedef unsigned long long ull;

// ---------------- scratch (__device__ globals; no allocation allowed) ----------------
__device__ float2 g_W2T2[(DD/2)*D2];
__device__ float  g_cb[DD];             // bt·Wt_row + bv·Wv_row
__device__ uint4  g_maskh4[BB*PROTO/8]; // bf16 0/1 presence mask (8MB)
__device__ __align__(16) __nv_bfloat16 g_PB2[2*128*1024];  // bf16 split protos^T [split][c][k]
__device__ __align__(16) __nv_bfloat16 g_WB2[2*128*KTOT];  // bf16 split [Wt|Wv]  [split][c][k]
__device__ __align__(16) __nv_bfloat16 g_W1B2[2*128*K1];   // bf16 split W1       [split][c][k]
__device__ __align__(16) __nv_bfloat16 g_XB[2*BB*KTOT];    // bf16 split gathered features
__device__ __align__(16) __nv_bfloat16 g_IFB[2*BB*K1];     // bf16 split inter_feat
__device__ float  g_cinv[BB];           // 1/unique-count
__device__ float  g_z1[BB*DD];
__device__ float  g_z2[BB*D2];
__device__ float  g_s1[DD], g_q1[DD];
__device__ float  g_s2[D2], g_q2[D2];

__device__ __forceinline__ void ffma2(ull &acc, ull a, ull b) {
    asm("fma.rn.f32x2 %0, %1, %2, %0;" : "+l"(acc) : "l"(a), "l"(b));
}
__device__ __forceinline__ float sum2(ull v) {
    return __uint_as_float((unsigned)v) + __uint_as_float((unsigned)(v >> 32));
}
__device__ __forceinline__ void cpa16(void* dst, const void* src) {
    unsigned d = (unsigned)__cvta_generic_to_shared(dst);
    asm volatile("cp.async.cg.shared.global [%0], [%1], 16;" :: "r"(d), "l"(src));
}
__device__ __forceinline__ void cpa_commit() { asm volatile("cp.async.commit_group;"); }
__device__ __forceinline__ void cpa_wait1() { asm volatile("cp.async.wait_group 1;"); }
__device__ __forceinline__ void cpa_wait0() { asm volatile("cp.async.wait_group 0;"); }

// HMMA bf16: D(f32) += A(bf16 m16k16 row) * B(bf16 k16n8 col)
__device__ __forceinline__ void mma_bf16(float* d, uint32_t a0, uint32_t a1,
                                         uint32_t a2, uint32_t a3,
                                         uint32_t b0, uint32_t b1) {
    asm volatile("mma.sync.aligned.m16n8k16.row.col.f32.bf16.bf16.f32 "
                 "{%0,%1,%2,%3},{%4,%5,%6,%7},{%8,%9},{%0,%1,%2,%3};"
                 : "+f"(d[0]), "+f"(d[1]), "+f"(d[2]), "+f"(d[3])
                 : "r"(a0), "r"(a1), "r"(a2), "r"(a3), "r"(b0), "r"(b1));
}
__device__ __forceinline__ uint32_t pk_bf2(float lo, float hi) {
    uint32_t r;
    asm("cvt.rn.bf16x2.f32 %0, %1, %2;" : "=r"(r) : "f"(hi), "f"(lo));
    return r;
}
__device__ __forceinline__ void split2(float v0, float v1, uint32_t &hi, uint32_t &lo) {
    __nv_bfloat16 h0 = __float2bfloat16(v0), h1 = __float2bfloat16(v1);
    uint16_t u0, u1; memcpy(&u0, &h0, 2); memcpy(&u1, &h1, 2);
    hi = (uint32_t)u0 | ((uint32_t)u1 << 16);
    lo = pk_bf2(v0 - __bfloat162float(h0), v1 - __bfloat162float(h1));
}

// ---------------- prep body (runs as tail blocks of k_xp) ---------------------------
__device__ void prep_body(int blk, int tid,
                          const float* __restrict__ Wt, const float* __restrict__ Wv,
                          const float* __restrict__ W1, const float* __restrict__ W2,
                          const float* __restrict__ protos,
                          const float* __restrict__ bt, const float* __restrict__ bv) {
    if (blk >= 296) {   // cb part: 16 blocks x 8 warps = 128 columns (first 256 thr)
        if (tid >= 256) return;
        int c = (blk - 296)*8 + (tid >> 5);
        int l = tid & 31;
        float s = 0.f;
        for (int k = l; k < 384; k += 32) s += bt[k] * Wt[c*384 + k];
        for (int k = l; k < 768; k += 32) s += bv[k] * Wv[c*768 + k];
        #pragma unroll
        for (int o = 16; o; o >>= 1) s += __shfl_down_sync(0xffffffffu, s, o);
        if (l == 0) g_cb[c] = s;
        return;
    }
    const int n_wb = 128*KTOT;
    const int n_pb = 128*1024;
    const int n_w1 = 128*K1;
    const int n_w2 = (DD/2)*D2;
    const int n_z  = 2*DD + 2*D2;
    int total = n_wb + n_pb + n_w1 + n_w2 + n_z;
    for (int i = blk*288 + tid; i < total; i += 296*288) {
        if (i < n_wb) {
            int c = i / KTOT, k = i % KTOT;
            float v = (k < 384) ? Wt[c*384 + k] : Wv[c*768 + (k - 384)];
            __nv_bfloat16 b1 = __float2bfloat16(v);
            g_WB2[i]            = b1;
            g_WB2[128*KTOT + i] = __float2bfloat16(v - __bfloat162float(b1));
        } else if (i < n_wb + n_pb) {
            int j = i - n_wb; int c = j & 127; int k = j >> 7;
            float p = protos[k*DD + c];
            __nv_bfloat16 b1 = __float2bfloat16(p);
            g_PB2[c*1024 + k]          = b1;
            g_PB2[131072 + c*1024 + k] = __float2bfloat16(p - __bfloat162float(b1));
        } else if (i < n_wb + n_pb + n_w1) {
            int j = i - n_wb - n_pb;
            float v = W1[j];
            __nv_bfloat16 b1 = __float2bfloat16(v);
            g_W1B2[j]          = b1;
            g_W1B2[128*K1 + j] = __float2bfloat16(v - __bfloat162float(b1));
        } else if (i < n_wb + n_pb + n_w1 + n_w2) {
            int j = i - n_wb - n_pb - n_w1; int k2 = j / D2, c = j % D2;
            g_W2T2[j] = make_float2(W2[c*DD + 2*k2], W2[c*DD + 2*k2 + 1]);
        } else {
            int j = i - n_wb - n_pb - n_w1 - n_w2;
            if (j < DD)            g_s1[j] = 0.f;
            else if (j < 2*DD)     g_q1[j-DD] = 0.f;
            else if (j < 2*DD+D2)  g_s2[j-2*DD] = 0.f;
            else                   g_q2[j-2*DD-D2] = 0.f;
        }
    }
}

// ---------------- fused: feature gather/split + mask build + prompt gathers + prep --
__global__ void __launch_bounds__(288) k_xp(
        const int* __restrict__ nodes_u, const int* __restrict__ nodes_v,
        const int* __restrict__ nodes_d, const int* __restrict__ inter_items,
        const int* __restrict__ top_n,
        const float* __restrict__ pre_text, const float* __restrict__ pre_visual,
        const float* __restrict__ up, const float* __restrict__ dp,
        float* __restrict__ out_pu, float* __restrict__ out_pd,
        const float* __restrict__ Wt, const float* __restrict__ Wv,
        const float* __restrict__ W1, const float* __restrict__ W2,
        const float* __restrict__ protos,
        const float* __restrict__ bt, const float* __restrict__ bv) {
    __shared__ unsigned bm[PROTO/32];
    int tid = threadIdx.x;
    if (blockIdx.x >= BB) {
        prep_body(blockIdx.x - BB, tid, Wt, Wv, W1, W2, protos, bt, bv);
        return;
    }
    int s = blockIdx.x;
    int row = nodes_v[s];
    float4 v = (tid < 96) ? ((const float4*)(pre_text + (size_t)row*384))[tid]
                          : ((const float4*)(pre_visual + (size_t)row*768))[tid - 96];
    if (tid < 32) bm[tid] = 0u;
    __syncthreads();
    if (tid < HIST) {
        int item = inter_items[s*HIST + tid];
        int4 r1 = ((const int4*)top_n)[item];
        int4 r2 = ((const int4*)top_n)[item + ITEMS];
        atomicOr(&bm[r1.x >> 5], 1u << (r1.x & 31));
        atomicOr(&bm[r1.y >> 5], 1u << (r1.y & 31));
        atomicOr(&bm[r1.z >> 5], 1u << (r1.z & 31));
        atomicOr(&bm[r1.w >> 5], 1u << (r1.w & 31));
        atomicOr(&bm[r2.x >> 5], 1u << (r2.x & 31));
        atomicOr(&bm[r2.y >> 5], 1u << (r2.y & 31));
        atomicOr(&bm[r2.z >> 5], 1u << (r2.z & 31));
        atomicOr(&bm[r2.w >> 5], 1u << (r2.w & 31));
    }
    {
        uint32_t h0, l0, h1, l1;
        split2(v.x, v.y, h0, l0);
        split2(v.z, v.w, h1, l1);
        size_t off = (size_t)s*KTOT + 4*tid;
        *(uint2*)(g_XB + off)                   = make_uint2(h0, h1);
        *(uint2*)(g_XB + (size_t)BB*KTOT + off) = make_uint2(l0, l1);
    }
    __syncthreads();
    if (tid < 32) {
        unsigned c = __popc(bm[tid]);
        #pragma unroll
        for (int o = 16; o; o >>= 1) c += __shfl_down_sync(0xffffffffu, c, o);
        if (tid == 0) g_cinv[s] = 1.0f / (float)c;
    }
    if (tid < 128) {
        unsigned w = bm[tid >> 2];
        int sh = (tid & 3) * 8;
        uint32_t pk[4];
        #pragma unroll
        for (int q = 0; q < 4; ++q) {
            uint32_t lo = ((w >> (sh + 2*q)) & 1) ? 0x3F80u : 0u;
            uint32_t hi = ((w >> (sh + 2*q + 1)) & 1) ? 0x3F80u : 0u;
            pk[q] = lo | (hi << 16);
        }
        g_maskh4[(size_t)s*128 + tid] = make_uint4(pk[0], pk[1], pk[2], pk[3]);
        out_pu[s*DD + tid] = up[nodes_u[s]*DD + tid];
        out_pd[s*DD + tid] = dp[nodes_d[s]*DD + tid];
    }
}

// ===================================================================================
// HMMA GEMM: M=32 x N=128, BK=64, ALL splits staged per chunk, depth-2 pipeline.
// Buffer = A_hi(4.5K) + A_lo(4.5K) + B_hi(18K) + B_lo(18K) = 46080 B; x2 = 92160.
// Row stride 72 bf16 (144B). Warp w covers cols [w*16, w*16+16).
// ===================================================================================
#define BK     64
#define TA_SZ  (32*144)
#define TB_SZ  (128*144)
#define EH_BUF (2*TA_SZ + 2*TB_SZ)   // 46080
#define EH_SMEM (2*EH_BUF)           // 92160

#define MMA_DECL                                                                \
    int tid = threadIdx.x;                                                      \
    int w = tid >> 5, lane = tid & 31;                                          \
    int gr = lane >> 2, kb = (lane & 3) * 2;                                    \
    float d[2][2][4];                                                           \
    _Pragma("unroll")                                                           \
    for (int mi = 0; mi < 2; ++mi)                                              \
        _Pragma("unroll")                                                       \
        for (int ni = 0; ni < 2; ++ni)                                          \
            _Pragma("unroll")                                                   \
            for (int q = 0; q < 4; ++q) d[mi][ni][q] = 0.f;

#define LOAD_A(dst, SRC, r0, k)                                                 \
    dst[0] = *(const uint32_t*)&SRC[(r0)*72 + (k)];                             \
    dst[1] = *(const uint32_t*)&SRC[((r0)+8)*72 + (k)];                         \
    dst[2] = *(const uint32_t*)&SRC[(r0)*72 + (k) + 8];                         \
    dst[3] = *(const uint32_t*)&SRC[((r0)+8)*72 + (k) + 8];

// ---------------- e body: per chunk stage {A1,A2,B1,B2}, 3 term-groups --------------
__device__ __forceinline__ void e_body(char* sm, int blk,
                                       const int* __restrict__ nodes_v,
                                       const float* __restrict__ ip) {
    MMA_DECL;
    auto stage = [&](int ch, int b) {
        char* base = sm + b*EH_BUF;
        int kk = ch * BK;
        #pragma unroll
        for (int sa = 0; sa < 2; ++sa) {
            const char* src = (const char*)g_XB
                + ((size_t)sa*BB + blk*32 + (tid >> 3))*(KTOT*2) + kk*2 + (tid & 7)*16;
            cpa16(base + sa*TA_SZ + (tid >> 3)*144 + (tid & 7)*16, src);
        }
        #pragma unroll
        for (int sb = 0; sb < 2; ++sb) {
            char* Bd = base + 2*TA_SZ + sb*TB_SZ;
            const char* bbase = (const char*)g_WB2 + (size_t)sb*128*KTOT*2;
            #pragma unroll
            for (int i = 0; i < 4; ++i) {
                int idx = tid + i*256; int c = idx >> 3, pc = idx & 7;
                cpa16(Bd + c*144 + pc*16, bbase + (size_t)c*(KTOT*2) + kk*2 + pc*16);
            }
        }
        cpa_commit();
    };

    const int NCH = KTOT/BK;   // 18
    stage(0, 0);
    #pragma unroll 1
    for (int ch = 0; ch < NCH; ++ch) {
        __syncthreads();
        if (ch + 1 < NCH) { stage(ch + 1, (ch + 1) & 1); cpa_wait1(); }
        else cpa_wait0();
        __syncthreads();
        const char* base = sm + (ch & 1)*EH_BUF;
        const __nv_bfloat16* A1 = (const __nv_bfloat16*)base;
        const __nv_bfloat16* A2 = (const __nv_bfloat16*)(base + TA_SZ);
        const __nv_bfloat16* B1 = (const __nv_bfloat16*)(base + 2*TA_SZ);
        const __nv_bfloat16* B2 = (const __nv_bfloat16*)(base + 2*TA_SZ + TB_SZ);
        #pragma unroll
        for (int ks = 0; ks < BK/16; ++ks) {
            int k = ks*16 + kb;
            uint32_t a1[2][4], a2[2][4];
            #pragma unroll
            for (int mi = 0; mi < 2; ++mi) {
                int r0 = mi*16 + gr;
                LOAD_A(a1[mi], A1, r0, k);
                LOAD_A(a2[mi], A2, r0, k);
            }
            #pragma unroll
            for (int ni = 0; ni < 2; ++ni) {
                int n = w*16 + ni*8 + gr;
                uint32_t b10 = *(const uint32_t*)&B1[n*72 + k];
                uint32_t b11 = *(const uint32_t*)&B1[n*72 + k + 8];
                uint32_t b20 = *(const uint32_t*)&B2[n*72 + k];
                uint32_t b21 = *(const uint32_t*)&B2[n*72 + k + 8];
                #pragma unroll
                for (int mi = 0; mi < 2; ++mi) {
                    mma_bf16(d[mi][ni], a1[mi][0], a1[mi][1], a1[mi][2], a1[mi][3], b10, b11);
                    mma_bf16(d[mi][ni], a1[mi][0], a1[mi][1], a1[mi][2], a1[mi][3], b20, b21);
                    mma_bf16(d[mi][ni], a2[mi][0], a2[mi][1], a2[mi][2], a2[mi][3], b10, b11);
                }
            }
        }
    }
    #pragma unroll
    for (int mi = 0; mi < 2; ++mi) {
        #pragma unroll
        for (int rr = 0; rr < 2; ++rr) {
            int s = blk*32 + mi*16 + gr + rr*8;
            int iv = nodes_v[s];
            #pragma unroll
            for (int ni = 0; ni < 2; ++ni) {
                int c = w*16 + ni*8 + (lane & 3)*2;
                float2 cbv = *(const float2*)&g_cb[c];
                float2 ipv = *(const float2*)&ip[(size_t)iv*DD + c];
                float e0 = d[mi][ni][rr*2]   - cbv.x + ipv.x;
                float e1 = d[mi][ni][rr*2+1] - cbv.y + ipv.y;
                uint32_t hi, lo;
                split2(e0, e1, hi, lo);
                *(uint32_t*)&g_IFB[(size_t)s*K1 + DD + c]        = hi;
                *(uint32_t*)&g_IFB[(size_t)(BB + s)*K1 + DD + c] = lo;
            }
        }
    }
}

// ---------------- hu body: per chunk stage {A, B1, B2}, 2 term-groups ---------------
__device__ __forceinline__ void hu_body(char* sm, int blk,
                                        const int* __restrict__ nodes_d,
                                        const float* __restrict__ dp,
                                        float* __restrict__ out_hu) {
    MMA_DECL;
    auto stage = [&](int ch, int b) {
        char* base = sm + b*EH_BUF;
        int kk = ch * BK;
        const char* asrc = (const char*)g_maskh4
                         + (size_t)(blk*32 + (tid >> 3))*2048 + kk*2 + (tid & 7)*16;
        cpa16(base + (tid >> 3)*144 + (tid & 7)*16, asrc);
        #pragma unroll
        for (int sb = 0; sb < 2; ++sb) {
            char* Bd = base + 2*TA_SZ + sb*TB_SZ;
            const char* bbase = (const char*)g_PB2 + ((size_t)sb << 18);
            #pragma unroll
            for (int i = 0; i < 4; ++i) {
                int idx = tid + i*256; int c = idx >> 3, pc = idx & 7;
                cpa16(Bd + c*144 + pc*16, bbase + (size_t)c*2048 + kk*2 + pc*16);
            }
        }
        cpa_commit();
    };

    const int NCH = PROTO/BK;  // 16
    stage(0, 0);
    #pragma unroll 1
    for (int ch = 0; ch < NCH; ++ch) {
        __syncthreads();
        if (ch + 1 < NCH) { stage(ch + 1, (ch + 1) & 1); cpa_wait1(); }
        else cpa_wait0();
        __syncthreads();
        const char* base = sm + (ch & 1)*EH_BUF;
        const __nv_bfloat16* A  = (const __nv_bfloat16*)base;
        const __nv_bfloat16* B1 = (const __nv_bfloat16*)(base + 2*TA_SZ);
        const __nv_bfloat16* B2 = (const __nv_bfloat16*)(base + 2*TA_SZ + TB_SZ);
        #pragma unroll
        for (int ks = 0; ks < BK/16; ++ks) {
            int k = ks*16 + kb;
            uint32_t a[2][4];
            #pragma unroll
            for (int mi = 0; mi < 2; ++mi) {
                int r0 = mi*16 + gr;
                LOAD_A(a[mi], A, r0, k);
            }
            #pragma unroll
            for (int ni = 0; ni < 2; ++ni) {
                int n = w*16 + ni*8 + gr;
                uint32_t b10 = *(const uint32_t*)&B1[n*72 + k];
                uint32_t b11 = *(const uint32_t*)&B1[n*72 + k + 8];
                uint32_t b20 = *(const uint32_t*)&B2[n*72 + k];
                uint32_t b21 = *(const uint32_t*)&B2[n*72 + k + 8];
                #pragma unroll
                for (int mi = 0; mi < 2; ++mi) {
                    mma_bf16(d[mi][ni], a[mi][0], a[mi][1], a[mi][2], a[mi][3], b10, b11);
                    mma_bf16(d[mi][ni], a[mi][0], a[mi][1], a[mi][2], a[mi][3], b20, b21);
                }
            }
        }
    }
    #pragma unroll
    for (int mi = 0; mi < 2; ++mi) {
        #pragma unroll
        for (int rr = 0; rr < 2; ++rr) {
            int s = blk*32 + mi*16 + gr + rr*8;
            float inv = g_cinv[s];
            const float* pdr = dp + nodes_d[s]*DD;
            #pragma unroll
            for (int ni = 0; ni < 2; ++ni) {
                int c = w*16 + ni*8 + (lane & 3)*2;
                float h0 = d[mi][ni][rr*2]   * inv;
                float h1 = d[mi][ni][rr*2+1] * inv;
                *(float2*)&out_hu[s*DD + c] = make_float2(h0, h1);
                float2 pd = *(const float2*)&pdr[c];
                uint32_t hi, lo;
                split2(h0 + pd.x, h1 + pd.y, hi, lo);
                *(uint32_t*)&g_IFB[(size_t)s*K1 + c]        = hi;
                *(uint32_t*)&g_IFB[(size_t)(BB + s)*K1 + c] = lo;
            }
        }
    }
}

// fused: blocks [0,128) do e, [128,256) do hu
__global__ void __launch_bounds__(256) k_eh(const int* __restrict__ nodes_v,
                                            const float* __restrict__ ip,
                                            const int* __restrict__ nodes_d,
                                            const float* __restrict__ dp,
                                            float* __restrict__ out_hu) {
    extern __shared__ char sm[];
    if (blockIdx.x < 128) e_body(sm, blockIdx.x, nodes_v, ip);
    else                  hu_body(sm, blockIdx.x - 128, nodes_d, dp, out_hu);
}

// ---------------- z1 via mma.sync, FULL-STAGE variant (R12, kept) -------------------
#define Z1_ST    264
#define Z1_ROWB  528
#define Z1_AOFF  0
#define Z1_BOFF  (64*Z1_ROWB)
#define Z1_SMEM  (64*Z1_ROWB + 256*Z1_ROWB)   // 168960 B

__global__ void __launch_bounds__(256) k_z1m(const float* __restrict__ b1) {
    extern __shared__ char sm[];
    int blk = blockIdx.x;
    MMA_DECL;
    {
        #pragma unroll
        for (int i = 0; i < 8; ++i) {
            int idx = tid + i*256;
            int r = idx >> 5, pc = idx & 31;
            int sa = r >> 5, smp = r & 31;
            const char* src = (const char*)g_IFB + (size_t)sa*BB*K1*2
                            + (size_t)(blk*32 + smp)*(K1*2) + pc*16;
            cpa16(sm + Z1_AOFF + r*Z1_ROWB + pc*16, src);
        }
        #pragma unroll
        for (int i = 0; i < 32; ++i) {
            int idx = tid + i*256;
            int r = idx >> 5, pc = idx & 31;
            const char* src = (const char*)g_W1B2 + (size_t)r*(K1*2) + pc*16;
            cpa16(sm + Z1_BOFF + r*Z1_ROWB + pc*16, src);
        }
        cpa_commit();
    }
    cpa_wait0();
    __syncthreads();
    #pragma unroll 1
    for (int ch = 0; ch < 12; ++ch) {
        int seg = ch >> 2;
        int k0 = (ch & 3) * BK;
        int sa = (seg == 2) ? 1 : 0;
        int sb = (seg == 1) ? 1 : 0;
        const __nv_bfloat16* A = (const __nv_bfloat16*)(sm + Z1_AOFF + sa*32*Z1_ROWB) + k0;
        const __nv_bfloat16* B = (const __nv_bfloat16*)(sm + Z1_BOFF + sb*128*Z1_ROWB) + k0;
        #pragma unroll
        for (int ks = 0; ks < BK/16; ++ks) {
            int k = ks*16 + kb;
            #pragma unroll
            for (int mi = 0; mi < 2; ++mi) {
                int r0 = mi*16 + gr;
                uint32_t a0 = *(const uint32_t*)&A[r0*Z1_ST + k];
                uint32_t a1 = *(const uint32_t*)&A[(r0+8)*Z1_ST + k];
                uint32_t a2 = *(const uint32_t*)&A[r0*Z1_ST + k + 8];
                uint32_t a3 = *(const uint32_t*)&A[(r0+8)*Z1_ST + k + 8];
                #pragma unroll
                for (int ni = 0; ni < 2; ++ni) {
                    int n = w*16 + ni*8 + gr;
                    uint32_t b0 = *(const uint32_t*)&B[n*Z1_ST + k];
                    uint32_t b1v = *(const uint32_t*)&B[n*Z1_ST + k + 8];
                    mma_bf16(d[mi][ni], a0, a1, a2, a3, b0, b1v);
                }
            }
        }
    }
    float2 bb[2];
    bb[0] = *(const float2*)&b1[w*16 + (lane & 3)*2];
    bb[1] = *(const float2*)&b1[w*16 + 8 + (lane & 3)*2];
    float ps[2][2] = {{0,0},{0,0}}, pq[2][2] = {{0,0},{0,0}};
    #pragma unroll
    for (int mi = 0; mi < 2; ++mi) {
        #pragma unroll
        for (int rr = 0; rr < 2; ++rr) {
            int s = blk*32 + mi*16 + gr + rr*8;
            #pragma unroll
            for (int ni = 0; ni < 2; ++ni) {
                int c = w*16 + ni*8 + (lane & 3)*2;
                float z0 = d[mi][ni][rr*2]   + bb[ni].x; z0 = z0 > 0.f ? z0 : 0.f;
                float z1v = d[mi][ni][rr*2+1] + bb[ni].y; z1v = z1v > 0.f ? z1v : 0.f;
                *(float2*)&g_z1[s*DD + c] = make_float2(z0, z1v);
                ps[ni][0] += z0; ps[ni][1] += z1v;
                pq[ni][0] += z0*z0; pq[ni][1] += z1v*z1v;
            }
        }
    }
    #pragma unroll
    for (int ni = 0; ni < 2; ++ni) {
        #pragma unroll
        for (int q = 0; q < 2; ++q) {
            #pragma unroll
            for (int o = 4; o <= 16; o <<= 1) {
                ps[ni][q] += __shfl_xor_sync(0xffffffffu, ps[ni][q], o);
                pq[ni][q] += __shfl_xor_sync(0xffffffffu, pq[ni][q], o);
            }
        }
        if (lane < 4) {
            int c = w*16 + ni*8 + lane*2;
            atomicAdd(&g_s1[c],   ps[ni][0]); atomicAdd(&g_s1[c+1], ps[ni][1]);
            atomicAdd(&g_q1[c],   pq[ni][0]); atomicAdd(&g_q1[c+1], pq[ni][1]);
        }
    }
}

// ---------------- z2 = relu(BN(z1) @ W2^T + b2) + partial BN stats (fold inline) ----
__global__ void __launch_bounds__(128) k_z2(const float* __restrict__ b2,
                                            const float* __restrict__ g1,
                                            const float* __restrict__ be1) {
    __shared__ __align__(16) float2 W2s[(DD/2)*D2];  // 32KB
    __shared__ __align__(16) float X[ESG][DD];       // 8KB
    __shared__ float A1[DD], D1[DD];
    int blk = blockIdx.x, tid = threadIdx.x;
    int c = tid & 63, h = tid >> 6;
    {
        const float4* src = (const float4*)g_W2T2;
        float4* dst = (float4*)W2s;
        #pragma unroll
        for (int i = 0; i < 16; ++i)
            cpa16(dst + tid + i*128, src + tid + i*128);
        cpa_commit();
    }
    if (tid < DD) {
        float m = g_s1[tid] * (1.0f/BB);
        float v = g_q1[tid] * (1.0f/BB) - m*m;
        float r = rsqrtf(v + 1e-5f);
        float a = g1[tid] * r;
        A1[tid] = a;
        D1[tid] = be1[tid] - m*a;
    }
    __syncthreads();
    for (int l = tid; l < ESG*DD; l += 128) {
        int s = l >> 7, kk = l & 127;
        X[s][kk] = g_z1[(blk*ESG + s)*DD + kk] * A1[kk] + D1[kk];
    }
    cpa_wait0();
    __syncthreads();
    ull acc[8];
    #pragma unroll
    for (int i = 0; i < 8; ++i) acc[i] = 0ull;
    #pragma unroll 8
    for (int p = 0; p < DD/2; ++p) {
        ull wv = *(const ull*)&W2s[p*D2 + c];
        #pragma unroll
        for (int i = 0; i < 8; ++i) {
            ull x = *(const ull*)&X[h*8 + i][2*p];
            ffma2(acc[i], wv, x);
        }
    }
    float bb = b2[c];
    float lsum = 0.f, lss = 0.f;
    #pragma unroll
    for (int i = 0; i < 8; ++i) {
        float z = sum2(acc[i]) + bb;
        z = z > 0.f ? z : 0.f;
        g_z2[(blk*ESG + h*8 + i)*D2 + c] = z;
        lsum += z; lss += z*z;
    }
    atomicAdd(&g_s2[c], lsum);
    atomicAdd(&g_q2[c], lss);
}

// ---------------- pred = sigmoid(BN(z2) @ Wp^T + bp), BN fold inline ---------------
__global__ void k_pred(const float* __restrict__ Wp, const float* __restrict__ bp,
                       const float* __restrict__ g2, const float* __restrict__ be2,
                       float* __restrict__ out_pred) {
    __shared__ float A2[D2], D2v[D2];
    int tid = threadIdx.x;
    if (tid < D2) {
        float m = g_s2[tid] * (1.0f/BB);
        float v = g_q2[tid] * (1.0f/BB) - m*m;
        float r = rsqrtf(v + 1e-5f);
        float a = g2[tid] * r;
        A2[tid] = a;
        D2v[tid] = be2[tid] - m*a;
    }
    __syncthreads();
    int warp = (blockIdx.x*blockDim.x + tid) >> 5;
    int lane = tid & 31;
    if (warp >= BB) return;
    float t = 0.f;
    #pragma unroll
    for (int j = 0; j < 2; ++j) {
        int cidx = lane + j*32;
        float f2 = g_z2[warp*D2 + cidx] * A2[cidx] + D2v[cidx];
        t += f2 * Wp[cidx];
    }
    #pragma unroll
    for (int o = 16; o; o >>= 1) t += __shfl_down_sync(0xffffffffu, t, o);
    if (lane == 0) out_pred[warp] = 1.0f / (1.0f + expf(-(t + bp[0])));
}

// ---------------- launch ------------------------------------------------------------
extern "C" void kernel_launch(void* const* d_in, const int* in_sizes, int n_in,
                              void* d_out, int out_size) {
    const int*   nodes_u     = (const int*)  d_in[0];
    const int*   nodes_v     = (const int*)  d_in[1];
    const int*   nodes_d     = (const int*)  d_in[2];
    const int*   inter_items = (const int*)  d_in[3];
    const int*   top_n       = (const int*)  d_in[4];
    const float* protos      = (const float*)d_in[5];
    const float* pre_text    = (const float*)d_in[6];
    const float* pre_visual  = (const float*)d_in[7];
    const float* Wt          = (const float*)d_in[8];
    const float* bt          = (const float*)d_in[9];
    const float* Wv          = (const float*)d_in[10];
    const float* bv          = (const float*)d_in[11];
    const float* up          = (const float*)d_in[12];
    const float* ip          = (const float*)d_in[13];
    const float* dp          = (const float*)d_in[14];
    const float* W1          = (const float*)d_in[15];
    const float* b1          = (const float*)d_in[16];
    const float* g1          = (const float*)d_in[17];
    const float* be1         = (const float*)d_in[18];
    const float* W2          = (const float*)d_in[19];
    const float* b2          = (const float*)d_in[20];
    const float* g2          = (const float*)d_in[21];
    const float* be2         = (const float*)d_in[22];
    const float* Wp          = (const float*)d_in[23];
    const float* bp          = (const float*)d_in[24];

    float* out      = (float*)d_out;
    float* out_pred = out;
    float* out_pu   = out + BB;
    float* out_hu   = out + BB + BB*DD;
    float* out_pd   = out + BB + 2*BB*DD;

    cudaFuncSetAttribute(k_eh,  cudaFuncAttributeMaxDynamicSharedMemorySize, EH_SMEM);
    cudaFuncSetAttribute(k_z1m, cudaFuncAttributeMaxDynamicSharedMemorySize, Z1_SMEM);

    k_xp<<<BB + 312, 288>>>(nodes_u, nodes_v, nodes_d, inter_items, top_n,
                            pre_text, pre_visual, up, dp, out_pu, out_pd,
                            Wt, Wv, W1, W2, protos, bt, bv);
    k_eh<<<256, 256, EH_SMEM>>>(nodes_v, ip, nodes_d, dp, out_hu);
    k_z1m<<<BB/32, 256, Z1_SMEM>>>(b1);
    k_z2<<<BB/ESG, 128>>>(b2, g1, be1);
    k_pred<<<BB/8, 256>>>(Wp, bp, g2, be2, out_pred);
}